// round 11
// baseline (speedup 1.0000x reference)
#include <cuda_runtime.h>
#include <cuda_fp16.h>
#include <cstdint>

#define N_NODES 50000
#define N_EDGES 800000
#define R_REL 8
#define NR (N_NODES * R_REL)
#define B_BASES 30
#define D0 128
#define D1 256
#define D2 512
#define K1 ((R_REL + 1) * D0)   // 1152
#define K2 ((R_REL + 1) * D1)   // 2304
#define BN_EPS 1e-5f
#define ALPHA 0.01f

#define HS 40                   // GEMM smem row stride in halfs (80B, 16B-aligned)

// ------------------------- scratch (__device__ globals) -------------------------
__device__ int    g_deg[NR];
__device__ int    g_off[NR + 1];
__device__ int    g_cur[NR];
__device__ int    g_bsums[512];
__device__ int    g_ssrc[N_EDGES];
__device__ float  g_W1[(size_t)K1 * D1];       // fp32 [K,N]
__device__ float  g_W2[(size_t)K2 * D2];
__device__ __half g_Wt1[(size_t)D1 * K1];      // fp16 [N,K]
__device__ __half g_Wt2[(size_t)D2 * K2];
__device__ __half g_Wft[(size_t)D2 * D2];
__device__ __half g_agg1[(size_t)N_NODES * K1];
__device__ __half g_agg2[(size_t)N_NODES * K2];
__device__ float  g_y1[(size_t)N_NODES * D1];
__device__ __half g_x1[(size_t)N_NODES * D1];
__device__ float  g_y2[(size_t)N_NODES * D2];
__device__ __half g_x2[(size_t)N_NODES * D2];
__device__ float  g_sum1[D1], g_sumsq1[D1];
__device__ float  g_sum2[D2], g_sumsq2[D2];
__device__ float  g_scale1[D1], g_shift1[D1];
__device__ float  g_scale2[D2], g_shift2[D2];

// ------------------------- small helpers -------------------------
__device__ __forceinline__ void mma_h(float (&d)[4], const uint32_t (&a)[4],
                                      const uint32_t (&b)[2]) {
    asm volatile(
        "mma.sync.aligned.m16n8k16.row.col.f32.f16.f16.f32 "
        "{%0,%1,%2,%3}, {%4,%5,%6,%7}, {%8,%9}, {%0,%1,%2,%3};"
        : "+f"(d[0]), "+f"(d[1]), "+f"(d[2]), "+f"(d[3])
        : "r"(a[0]), "r"(a[1]), "r"(a[2]), "r"(a[3]), "r"(b[0]), "r"(b[1]));
}
__device__ __forceinline__ void cp_async16(void* smem, const void* gmem, int src_bytes) {
    uint32_t s = (uint32_t)__cvta_generic_to_shared(smem);
    asm volatile("cp.async.cg.shared.global [%0], [%1], 16, %2;"
                 :: "r"(s), "l"(gmem), "r"(src_bytes));
}
__device__ __forceinline__ void cp_commit() {
    asm volatile("cp.async.commit_group;");
}

// ------------------------- setup kernels -------------------------
__global__ void zero_k() {
    int i = blockIdx.x * blockDim.x + threadIdx.x;
    int stride = gridDim.x * blockDim.x;
    for (int j = i; j < NR; j += stride) g_deg[j] = 0;
    if (i < D1) { g_sum1[i] = 0.f; g_sumsq1[i] = 0.f; }
    if (i < D2) { g_sum2[i] = 0.f; g_sumsq2[i] = 0.f; }
}

__global__ void hist_k(const int* __restrict__ tgt, const int* __restrict__ ety) {
    int e = blockIdx.x * blockDim.x + threadIdx.x;
    if (e < N_EDGES) atomicAdd(&g_deg[tgt[e] * R_REL + ety[e]], 1);
}

__global__ void scan1_k() {
    __shared__ int s[1024];
    int t = threadIdx.x;
    int i = blockIdx.x * 1024 + t;
    int v = (i < NR) ? g_deg[i] : 0;
    s[t] = v;
    __syncthreads();
#pragma unroll
    for (int off = 1; off < 1024; off <<= 1) {
        int u = (t >= off) ? s[t - off] : 0;
        __syncthreads();
        s[t] += u;
        __syncthreads();
    }
    if (i < NR) g_off[i] = s[t] - v;
    if (t == 1023) g_bsums[blockIdx.x] = s[1023];
}

__global__ void scan23_k(int nb) {
    __shared__ int s[512];
    __shared__ int ex[512];
    int t = threadIdx.x;
    int v = (t < nb) ? g_bsums[t] : 0;
    s[t] = v;
    __syncthreads();
#pragma unroll
    for (int off = 1; off < 512; off <<= 1) {
        int u = (t >= off) ? s[t - off] : 0;
        __syncthreads();
        s[t] += u;
        __syncthreads();
    }
    ex[t] = s[t] - v;
    __syncthreads();
    for (int i = blockIdx.x * blockDim.x + t; i < NR; i += gridDim.x * blockDim.x) {
        int o = g_off[i] + ex[i >> 10];
        g_off[i] = o;
        g_cur[i] = o;
    }
    if (blockIdx.x == 0 && t == 0) g_off[NR] = N_EDGES;
}

__global__ void scatter_k(const int* __restrict__ src, const int* __restrict__ tgt,
                          const int* __restrict__ ety) {
    int e = blockIdx.x * blockDim.x + threadIdx.x;
    if (e < N_EDGES) {
        int seg = tgt[e] * R_REL + ety[e];
        int p = atomicAdd(&g_cur[seg], 1);
        g_ssrc[p] = src[e];
    }
}

// W_cat[(r*Din+i)*Dout+o] = sum_b comp[r,b]*basis[b,i,o]; root appended (fp32)
__global__ void build_w_k(const float* __restrict__ basis,
                          const float* __restrict__ comp,
                          const float* __restrict__ root,
                          float* __restrict__ W, int Din, int Dout) {
    __shared__ float sc[R_REL * B_BASES];
    if (threadIdx.x < R_REL * B_BASES) sc[threadIdx.x] = comp[threadIdx.x];
    __syncthreads();
    int idx = blockIdx.x * blockDim.x + threadIdx.x;
    int total = Din * Dout;
    if (idx >= total) return;
    float acc[R_REL];
#pragma unroll
    for (int r = 0; r < R_REL; ++r) acc[r] = 0.f;
    for (int b = 0; b < B_BASES; ++b) {
        float v = basis[(size_t)b * total + idx];
#pragma unroll
        for (int r = 0; r < R_REL; ++r) acc[r] += sc[r * B_BASES + b] * v;
    }
#pragma unroll
    for (int r = 0; r < R_REL; ++r)
        W[(size_t)r * total + idx] = acc[r];
    W[(size_t)R_REL * total + idx] = root[idx];
}

// transpose + fp16 convert: dst[n][k] = (half)src[k][n].  grid (Nd/32, Kd/32)
__global__ void transpose_h_k(const float* __restrict__ src, __half* __restrict__ dst,
                              int Kd, int Nd) {
    __shared__ float t[32][33];
    int bx = blockIdx.x * 32;   // over N
    int by = blockIdx.y * 32;   // over K
    for (int j = threadIdx.y; j < 32; j += 8)
        t[j][threadIdx.x] = src[(size_t)(by + j) * Nd + bx + threadIdx.x];
    __syncthreads();
    for (int j = threadIdx.y; j < 32; j += 8)
        dst[(size_t)(bx + j) * Kd + by + threadIdx.x] = __float2half_rn(t[threadIdx.x][j]);
}

// ------------------------- aggregation (warp per (node,relation)) -------------------------
// layer 1: fp32 input (Din=128). warps [0,NR) do segment means; [NR, NR+N) self-copy.
__global__ void __launch_bounds__(256) agg1_k(const float* __restrict__ x,
                                              __half* __restrict__ agg) {
    int w = (blockIdx.x * blockDim.x + threadIdx.x) >> 5;
    int lane = threadIdx.x & 31;
    if (w < NR) {
        int n = w >> 3, r = w & 7;
        int s = g_off[w], e = g_off[w + 1];
        float4 acc = make_float4(0.f, 0.f, 0.f, 0.f);
        int j = s;
        for (; j + 1 < e; j += 2) {
            float4 v0 = ((const float4*)(x + (size_t)g_ssrc[j] * D0))[lane];
            float4 v1 = ((const float4*)(x + (size_t)g_ssrc[j + 1] * D0))[lane];
            acc.x += v0.x + v1.x; acc.y += v0.y + v1.y;
            acc.z += v0.z + v1.z; acc.w += v0.w + v1.w;
        }
        if (j < e) {
            float4 v = ((const float4*)(x + (size_t)g_ssrc[j] * D0))[lane];
            acc.x += v.x; acc.y += v.y; acc.z += v.z; acc.w += v.w;
        }
        float invd = (e > s) ? 1.0f / (float)(e - s) : 0.0f;
        __half2 h0 = __floats2half2_rn(acc.x * invd, acc.y * invd);
        __half2 h1 = __floats2half2_rn(acc.z * invd, acc.w * invd);
        *(uint2*)(agg + (size_t)n * K1 + r * D0 + lane * 4) =
            make_uint2(*(uint32_t*)&h0, *(uint32_t*)&h1);
    } else if (w < NR + N_NODES) {
        int n = w - NR;
        float4 v = ((const float4*)(x + (size_t)n * D0))[lane];
        __half2 h0 = __floats2half2_rn(v.x, v.y);
        __half2 h1 = __floats2half2_rn(v.z, v.w);
        *(uint2*)(agg + (size_t)n * K1 + R_REL * D0 + lane * 4) =
            make_uint2(*(uint32_t*)&h0, *(uint32_t*)&h1);
    }
}

// layer 2: fp16 input (Din=256)
__global__ void __launch_bounds__(256) agg2_k(const __half* __restrict__ x,
                                              __half* __restrict__ agg) {
    int w = (blockIdx.x * blockDim.x + threadIdx.x) >> 5;
    int lane = threadIdx.x & 31;
    if (w < NR) {
        int n = w >> 3, r = w & 7;
        int s = g_off[w], e = g_off[w + 1];
        float acc[8];
#pragma unroll
        for (int i = 0; i < 8; ++i) acc[i] = 0.f;
        int j = s;
        for (; j + 1 < e; j += 2) {
            uint4 u0 = ((const uint4*)(x + (size_t)g_ssrc[j] * D1))[lane];
            uint4 u1 = ((const uint4*)(x + (size_t)g_ssrc[j + 1] * D1))[lane];
            float2 a0 = __half22float2(*(__half2*)&u0.x), b0 = __half22float2(*(__half2*)&u1.x);
            float2 a1 = __half22float2(*(__half2*)&u0.y), b1 = __half22float2(*(__half2*)&u1.y);
            float2 a2 = __half22float2(*(__half2*)&u0.z), b2 = __half22float2(*(__half2*)&u1.z);
            float2 a3 = __half22float2(*(__half2*)&u0.w), b3 = __half22float2(*(__half2*)&u1.w);
            acc[0] += a0.x + b0.x; acc[1] += a0.y + b0.y;
            acc[2] += a1.x + b1.x; acc[3] += a1.y + b1.y;
            acc[4] += a2.x + b2.x; acc[5] += a2.y + b2.y;
            acc[6] += a3.x + b3.x; acc[7] += a3.y + b3.y;
        }
        if (j < e) {
            uint4 u0 = ((const uint4*)(x + (size_t)g_ssrc[j] * D1))[lane];
            float2 a0 = __half22float2(*(__half2*)&u0.x);
            float2 a1 = __half22float2(*(__half2*)&u0.y);
            float2 a2 = __half22float2(*(__half2*)&u0.z);
            float2 a3 = __half22float2(*(__half2*)&u0.w);
            acc[0] += a0.x; acc[1] += a0.y; acc[2] += a1.x; acc[3] += a1.y;
            acc[4] += a2.x; acc[5] += a2.y; acc[6] += a3.x; acc[7] += a3.y;
        }
        float invd = (e > s) ? 1.0f / (float)(e - s) : 0.0f;
        __half2 h0 = __floats2half2_rn(acc[0] * invd, acc[1] * invd);
        __half2 h1 = __floats2half2_rn(acc[2] * invd, acc[3] * invd);
        __half2 h2 = __floats2half2_rn(acc[4] * invd, acc[5] * invd);
        __half2 h3 = __floats2half2_rn(acc[6] * invd, acc[7] * invd);
        *(uint4*)(agg + (size_t)n * K2 + r * D1 + lane * 8) =
            make_uint4(*(uint32_t*)&h0, *(uint32_t*)&h1,
                       *(uint32_t*)&h2, *(uint32_t*)&h3);
    } else if (w < NR + N_NODES) {
        int n = w - NR;
        uint4 v = ((const uint4*)(x + (size_t)n * D1))[lane];
        *(uint4*)(agg + (size_t)n * K2 + R_REL * D1 + lane * 8) = v;
    }
}

// ------------------------- fp16 tensor-core GEMM (+fused BN stats) -------------------------
// C[M,Nn] = A[M,K] @ Bt[Nn,K]^T + bias.  fp16 in, fp32 accum/out.
// Block 128x128, BK=32, 2-stage cp.async. 8 warps (4M x 2N), warp tile 32x64.
// STATS: per-column sum/sumsq accumulated in smem (stage buffers reused), one
// global atomic per column per CTA.
template <bool STATS>
__global__ void __launch_bounds__(256, 2) gemm_h_k(
    const __half* __restrict__ A, const __half* __restrict__ Bt,
    const float* __restrict__ bias, float* __restrict__ C,
    float* __restrict__ gsum, float* __restrict__ gsumsq,
    int M, int Nn, int K) {
    __shared__ __align__(16) __half As[2][128 * HS];
    __shared__ __align__(16) __half Bs[2][128 * HS];

    const int tid = threadIdx.x;
    const int lane = tid & 31, warp = tid >> 5;
    const int wm = warp >> 1, wn = warp & 1;
    const int gid = lane >> 2, tg = lane & 3;
    const int blockN = blockIdx.x * 128;
    const int blockM = blockIdx.y * 128;

    float acc[2][8][4];
#pragma unroll
    for (int mt = 0; mt < 2; ++mt)
#pragma unroll
        for (int nt = 0; nt < 8; ++nt)
#pragma unroll
            for (int c = 0; c < 4; ++c) acc[mt][nt][c] = 0.f;

    const int ktiles = K >> 5;

    auto load_stage = [&](int st, int kt) {
        int kbase = kt << 5;
#pragma unroll
        for (int it = 0; it < 2; ++it) {
            int idx = tid + it * 256;
            int row = idx >> 2, c16 = (idx & 3) << 3;
            int gr = blockM + row;
            int cr = gr < M ? gr : (M - 1);
            cp_async16(&As[st][row * HS + c16], A + (size_t)cr * K + kbase + c16,
                       gr < M ? 16 : 0);
            cp_async16(&Bs[st][row * HS + c16], Bt + (size_t)(blockN + row) * K + kbase + c16,
                       16);
        }
        cp_commit();
    };

    load_stage(0, 0);

    for (int kt = 0; kt < ktiles; ++kt) {
        int cur = kt & 1;
        if (kt + 1 < ktiles) {
            load_stage(cur ^ 1, kt + 1);
            asm volatile("cp.async.wait_group 1;");
        } else {
            asm volatile("cp.async.wait_group 0;");
        }
        __syncthreads();

        const __half* as = As[cur];
        const __half* bs = Bs[cur];
#pragma unroll
        for (int kk = 0; kk < 2; ++kk) {
            int k0 = kk * 16 + 2 * tg;
            uint32_t a[2][4];
#pragma unroll
            for (int mt = 0; mt < 2; ++mt) {
                int r0 = wm * 32 + mt * 16 + gid;
                a[mt][0] = *(const uint32_t*)&as[r0 * HS + k0];
                a[mt][1] = *(const uint32_t*)&as[(r0 + 8) * HS + k0];
                a[mt][2] = *(const uint32_t*)&as[r0 * HS + k0 + 8];
                a[mt][3] = *(const uint32_t*)&as[(r0 + 8) * HS + k0 + 8];
            }
            uint32_t b[8][2];
#pragma unroll
            for (int nt = 0; nt < 8; ++nt) {
                int c0 = wn * 64 + nt * 8 + gid;
                b[nt][0] = *(const uint32_t*)&bs[c0 * HS + k0];
                b[nt][1] = *(const uint32_t*)&bs[c0 * HS + k0 + 8];
            }
#pragma unroll
            for (int mt = 0; mt < 2; ++mt)
#pragma unroll
                for (int nt = 0; nt < 8; ++nt) mma_h(acc[mt][nt], a[mt], b[nt]);
        }
        __syncthreads();
    }

    // epilogue: bias + fp32 store (+ fused BN column stats in smem)
    float* colsum = (float*)As;        // stage buffers dead after final sync
    float* colsq = colsum + 128;
    if (STATS) {
        if (tid < 128) { colsum[tid] = 0.f; colsq[tid] = 0.f; }
        __syncthreads();
    }
#pragma unroll
    for (int nt = 0; nt < 8; ++nt) {
        int cb = wn * 64 + nt * 8 + 2 * tg;
        int col = blockN + cb;
        float bx = bias[col], by = bias[col + 1];
        float s0 = 0.f, q0 = 0.f, s1 = 0.f, q1 = 0.f;
#pragma unroll
        for (int mt = 0; mt < 2; ++mt) {
            int row0 = blockM + wm * 32 + mt * 16 + gid;
            if (row0 < M) {
                float v0 = acc[mt][nt][0] + bx;
                float v1 = acc[mt][nt][1] + by;
                *(float2*)(C + (size_t)row0 * Nn + col) = make_float2(v0, v1);
                if (STATS) { s0 += v0; q0 += v0 * v0; s1 += v1; q1 += v1 * v1; }
            }
            int row1 = row0 + 8;
            if (row1 < M) {
                float v0 = acc[mt][nt][2] + bx;
                float v1 = acc[mt][nt][3] + by;
                *(float2*)(C + (size_t)row1 * Nn + col) = make_float2(v0, v1);
                if (STATS) { s0 += v0; q0 += v0 * v0; s1 += v1; q1 += v1 * v1; }
            }
        }
        if (STATS) {
            atomicAdd(&colsum[cb], s0);
            atomicAdd(&colsq[cb], q0);
            atomicAdd(&colsum[cb + 1], s1);
            atomicAdd(&colsq[cb + 1], q1);
        }
    }
    if (STATS) {
        __syncthreads();
        if (tid < 128) {
            atomicAdd(&gsum[blockN + tid], colsum[tid]);
            atomicAdd(&gsumsq[blockN + tid], colsq[tid]);
        }
    }
}

// ------------------------- batchnorm finalize + apply -------------------------
__global__ void bnfin_k(const float* __restrict__ sum, const float* __restrict__ sumsq,
                        const float* __restrict__ gamma, const float* __restrict__ beta,
                        float* __restrict__ scale, float* __restrict__ shift, int C) {
    int c = blockIdx.x * blockDim.x + threadIdx.x;
    if (c >= C) return;
    const float invn = 1.0f / (float)N_NODES;
    float mu = sum[c] * invn;
    float var = sumsq[c] * invn - mu * mu;
    float sc = gamma[c] * rsqrtf(var + BN_EPS);
    scale[c] = sc;
    shift[c] = beta[c] - mu * sc;
}

// BN + LeakyReLU -> fp16 (feeds next GEMM / aggregation)
__global__ void bnapply_k(const float* __restrict__ y, const float* __restrict__ scale,
                          const float* __restrict__ shift, __half* __restrict__ x, int C) {
    size_t total = (size_t)N_NODES * C;
    size_t stride = (size_t)gridDim.x * blockDim.x;
    for (size_t i = blockIdx.x * (size_t)blockDim.x + threadIdx.x; i < total; i += stride) {
        int c = (int)(i % C);
        float v = y[i] * scale[c] + shift[c];
        v = v > 0.f ? v : ALPHA * v;
        x[i] = __float2half_rn(v);
    }
}

// ------------------------- host launch -------------------------
extern "C" void kernel_launch(void* const* d_in, const int* in_sizes, int n_in,
                              void* d_out, int out_size) {
    const float* emb    = (const float*)d_in[0];
    const int*   eidx   = (const int*)d_in[1];
    const int*   ety    = (const int*)d_in[2];
    const float* basis1 = (const float*)d_in[3];
    const float* comp1  = (const float*)d_in[4];
    const float* root1  = (const float*)d_in[5];
    const float* bias1  = (const float*)d_in[6];
    const float* gamma1 = (const float*)d_in[7];
    const float* beta1  = (const float*)d_in[8];
    const float* basis2 = (const float*)d_in[9];
    const float* comp2  = (const float*)d_in[10];
    const float* root2  = (const float*)d_in[11];
    const float* bias2  = (const float*)d_in[12];
    const float* gamma2 = (const float*)d_in[13];
    const float* beta2  = (const float*)d_in[14];
    const float* Wf     = (const float*)d_in[15];
    const float* bf     = (const float*)d_in[16];
    const int* srcp = eidx;
    const int* tgtp = eidx + N_EDGES;
    float* outp = (float*)d_out;

    float *W1, *W2, *y1, *y2;
    __half *Wt1, *Wt2, *Wft, *agg1, *agg2, *x1, *x2;
    float *sum1, *sumsq1, *sum2, *sumsq2, *scale1, *shift1, *scale2, *shift2;
    cudaGetSymbolAddress((void**)&W1, g_W1);
    cudaGetSymbolAddress((void**)&W2, g_W2);
    cudaGetSymbolAddress((void**)&Wt1, g_Wt1);
    cudaGetSymbolAddress((void**)&Wt2, g_Wt2);
    cudaGetSymbolAddress((void**)&Wft, g_Wft);
    cudaGetSymbolAddress((void**)&agg1, g_agg1);
    cudaGetSymbolAddress((void**)&agg2, g_agg2);
    cudaGetSymbolAddress((void**)&y1, g_y1);
    cudaGetSymbolAddress((void**)&x1, g_x1);
    cudaGetSymbolAddress((void**)&y2, g_y2);
    cudaGetSymbolAddress((void**)&x2, g_x2);
    cudaGetSymbolAddress((void**)&sum1, g_sum1);
    cudaGetSymbolAddress((void**)&sumsq1, g_sumsq1);
    cudaGetSymbolAddress((void**)&sum2, g_sum2);
    cudaGetSymbolAddress((void**)&sumsq2, g_sumsq2);
    cudaGetSymbolAddress((void**)&scale1, g_scale1);
    cudaGetSymbolAddress((void**)&shift1, g_shift1);
    cudaGetSymbolAddress((void**)&scale2, g_scale2);
    cudaGetSymbolAddress((void**)&shift2, g_shift2);

    const int TPB = 256;
    int nScanBlocks = (NR + 1023) / 1024;  // 391
    int aggBlocks = ((NR + N_NODES) * 32 + TPB - 1) / TPB;

    // CSR build
    zero_k<<<512, TPB>>>();
    hist_k<<<(N_EDGES + TPB - 1) / TPB, TPB>>>(tgtp, ety);
    scan1_k<<<nScanBlocks, 1024>>>();
    scan23_k<<<(NR + 511) / 512, 512>>>(nScanBlocks);
    scatter_k<<<(N_EDGES + TPB - 1) / TPB, TPB>>>(srcp, tgtp, ety);

    // weights: fp32 build, then transpose+fp16 convert
    build_w_k<<<(D0 * D1 + TPB - 1) / TPB, TPB>>>(basis1, comp1, root1, W1, D0, D1);
    build_w_k<<<(D1 * D2 + TPB - 1) / TPB, TPB>>>(basis2, comp2, root2, W2, D1, D2);
    transpose_h_k<<<dim3(D1 / 32, K1 / 32), dim3(32, 8)>>>(W1, Wt1, K1, D1);
    transpose_h_k<<<dim3(D2 / 32, K2 / 32), dim3(32, 8)>>>(W2, Wt2, K2, D2);
    transpose_h_k<<<dim3(D2 / 32, D2 / 32), dim3(32, 8)>>>(Wf, Wft, D2, D2);

    dim3 grid1(D1 / 128, (N_NODES + 127) / 128);
    dim3 grid2(D2 / 128, (N_NODES + 127) / 128);

    // layer 1: agg -> GEMM(+stats) -> finalize -> apply
    agg1_k<<<aggBlocks, TPB>>>(emb, agg1);
    gemm_h_k<true><<<grid1, 256>>>(agg1, Wt1, bias1, y1, sum1, sumsq1,
                                   N_NODES, D1, K1);
    bnfin_k<<<1, D1>>>(sum1, sumsq1, gamma1, beta1, scale1, shift1, D1);
    bnapply_k<<<8192, TPB>>>(y1, scale1, shift1, x1, D1);

    // layer 2
    agg2_k<<<aggBlocks, TPB>>>(x1, agg2);
    gemm_h_k<true><<<grid2, 256>>>(agg2, Wt2, bias2, y2, sum2, sumsq2,
                                   N_NODES, D2, K2);
    bnfin_k<<<1, D2>>>(sum2, sumsq2, gamma2, beta2, scale2, shift2, D2);
    bnapply_k<<<8192, TPB>>>(y2, scale2, shift2, x2, D2);

    // final linear
    gemm_h_k<false><<<grid2, 256>>>(x2, Wft, bf, outp, nullptr, nullptr,
                                    N_NODES, D2, D2);
}

// round 13
// speedup vs baseline: 1.0799x; 1.0799x over previous
#include <cuda_runtime.h>
#include <cuda_fp16.h>
#include <cstdint>

#define N_NODES 50000
#define N_EDGES 800000
#define R_REL 8
#define NR (N_NODES * R_REL)
#define B_BASES 30
#define D0 128
#define D1 256
#define D2 512
#define K1 ((R_REL + 1) * D0)   // 1152
#define K2 ((R_REL + 1) * D1)   // 2304
#define BN_EPS 1e-5f
#define ALPHA 0.01f

#define HS 40                   // GEMM smem row stride in halfs (80B, 16B-aligned)

// ------------------------- scratch (__device__ globals) -------------------------
__device__ int    g_deg[NR];
__device__ int    g_off[NR + 1];
__device__ int    g_cur[NR];
__device__ int    g_bsums[512];
__device__ int    g_ssrc[N_EDGES];
__device__ float  g_W1[(size_t)K1 * D1];       // fp32 [K,N]
__device__ float  g_W2[(size_t)K2 * D2];
__device__ __half g_Wt1[(size_t)D1 * K1];      // fp16 [N,K]
__device__ __half g_Wt2[(size_t)D2 * K2];
__device__ __half g_Wft[(size_t)D2 * D2];
__device__ __half g_agg1[(size_t)N_NODES * K1];
__device__ __half g_agg2[(size_t)N_NODES * K2];
__device__ float  g_y1[(size_t)N_NODES * D1];
__device__ __half g_x1[(size_t)N_NODES * D1];
__device__ float  g_y2[(size_t)N_NODES * D2];
__device__ __half g_x2[(size_t)N_NODES * D2];
__device__ float  g_sum1[D1], g_sumsq1[D1];
__device__ float  g_sum2[D2], g_sumsq2[D2];
__device__ float  g_scale1[D1], g_shift1[D1];
__device__ float  g_scale2[D2], g_shift2[D2];

// ------------------------- small helpers -------------------------
__device__ __forceinline__ void mma_h(float (&d)[4], const uint32_t (&a)[4],
                                      const uint32_t (&b)[2]) {
    asm volatile(
        "mma.sync.aligned.m16n8k16.row.col.f32.f16.f16.f32 "
        "{%0,%1,%2,%3}, {%4,%5,%6,%7}, {%8,%9}, {%0,%1,%2,%3};"
        : "+f"(d[0]), "+f"(d[1]), "+f"(d[2]), "+f"(d[3])
        : "r"(a[0]), "r"(a[1]), "r"(a[2]), "r"(a[3]), "r"(b[0]), "r"(b[1]));
}
__device__ __forceinline__ void cp_async16(void* smem, const void* gmem, int src_bytes) {
    uint32_t s = (uint32_t)__cvta_generic_to_shared(smem);
    asm volatile("cp.async.cg.shared.global [%0], [%1], 16, %2;"
                 :: "r"(s), "l"(gmem), "r"(src_bytes));
}
__device__ __forceinline__ void cp_commit() {
    asm volatile("cp.async.commit_group;");
}

// ------------------------- setup kernels -------------------------
__global__ void zero_k() {
    int i = blockIdx.x * blockDim.x + threadIdx.x;
    int stride = gridDim.x * blockDim.x;
    for (int j = i; j < NR; j += stride) g_deg[j] = 0;
    if (i < D1) { g_sum1[i] = 0.f; g_sumsq1[i] = 0.f; }
    if (i < D2) { g_sum2[i] = 0.f; g_sumsq2[i] = 0.f; }
}

__global__ void hist_k(const int* __restrict__ tgt, const int* __restrict__ ety) {
    int e = blockIdx.x * blockDim.x + threadIdx.x;
    if (e < N_EDGES) atomicAdd(&g_deg[tgt[e] * R_REL + ety[e]], 1);
}

__global__ void scan1_k() {
    __shared__ int s[1024];
    int t = threadIdx.x;
    int i = blockIdx.x * 1024 + t;
    int v = (i < NR) ? g_deg[i] : 0;
    s[t] = v;
    __syncthreads();
#pragma unroll
    for (int off = 1; off < 1024; off <<= 1) {
        int u = (t >= off) ? s[t - off] : 0;
        __syncthreads();
        s[t] += u;
        __syncthreads();
    }
    if (i < NR) g_off[i] = s[t] - v;
    if (t == 1023) g_bsums[blockIdx.x] = s[1023];
}

__global__ void scan23_k(int nb) {
    __shared__ int s[512];
    __shared__ int ex[512];
    int t = threadIdx.x;
    int v = (t < nb) ? g_bsums[t] : 0;
    s[t] = v;
    __syncthreads();
#pragma unroll
    for (int off = 1; off < 512; off <<= 1) {
        int u = (t >= off) ? s[t - off] : 0;
        __syncthreads();
        s[t] += u;
        __syncthreads();
    }
    ex[t] = s[t] - v;
    __syncthreads();
    for (int i = blockIdx.x * blockDim.x + t; i < NR; i += gridDim.x * blockDim.x) {
        int o = g_off[i] + ex[i >> 10];
        g_off[i] = o;
        g_cur[i] = o;
    }
    if (blockIdx.x == 0 && t == 0) g_off[NR] = N_EDGES;
}

__global__ void scatter_k(const int* __restrict__ src, const int* __restrict__ tgt,
                          const int* __restrict__ ety) {
    int e = blockIdx.x * blockDim.x + threadIdx.x;
    if (e < N_EDGES) {
        int seg = tgt[e] * R_REL + ety[e];
        int p = atomicAdd(&g_cur[seg], 1);
        g_ssrc[p] = src[e];
    }
}

// W_cat[(r*Din+i)*Dout+o] = sum_b comp[r,b]*basis[b,i,o]; root appended (fp32)
__global__ void build_w_k(const float* __restrict__ basis,
                          const float* __restrict__ comp,
                          const float* __restrict__ root,
                          float* __restrict__ W, int Din, int Dout) {
    __shared__ float sc[R_REL * B_BASES];
    if (threadIdx.x < R_REL * B_BASES) sc[threadIdx.x] = comp[threadIdx.x];
    __syncthreads();
    int idx = blockIdx.x * blockDim.x + threadIdx.x;
    int total = Din * Dout;
    if (idx >= total) return;
    float acc[R_REL];
#pragma unroll
    for (int r = 0; r < R_REL; ++r) acc[r] = 0.f;
    for (int b = 0; b < B_BASES; ++b) {
        float v = basis[(size_t)b * total + idx];
#pragma unroll
        for (int r = 0; r < R_REL; ++r) acc[r] += sc[r * B_BASES + b] * v;
    }
#pragma unroll
    for (int r = 0; r < R_REL; ++r)
        W[(size_t)r * total + idx] = acc[r];
    W[(size_t)R_REL * total + idx] = root[idx];
}

// transpose + fp16 convert: dst[n][k] = (half)src[k][n].  grid (Nd/32, Kd/32)
__global__ void transpose_h_k(const float* __restrict__ src, __half* __restrict__ dst,
                              int Kd, int Nd) {
    __shared__ float t[32][33];
    int bx = blockIdx.x * 32;   // over N
    int by = blockIdx.y * 32;   // over K
    for (int j = threadIdx.y; j < 32; j += 8)
        t[j][threadIdx.x] = src[(size_t)(by + j) * Nd + bx + threadIdx.x];
    __syncthreads();
    for (int j = threadIdx.y; j < 32; j += 8)
        dst[(size_t)(bx + j) * Kd + by + threadIdx.x] = __float2half_rn(t[threadIdx.x][j]);
}

// ------------------------- aggregation (warp per (node,relation)) -------------------------
// layer 1: fp32 input (Din=128). warps [0,NR) do segment means; [NR, NR+N) self-copy.
__global__ void __launch_bounds__(256) agg1_k(const float* __restrict__ x,
                                              __half* __restrict__ agg) {
    int w = (blockIdx.x * blockDim.x + threadIdx.x) >> 5;
    int lane = threadIdx.x & 31;
    if (w < NR) {
        int n = w >> 3, r = w & 7;
        int s = g_off[w], e = g_off[w + 1];
        float4 acc = make_float4(0.f, 0.f, 0.f, 0.f);
        int j = s;
        for (; j + 1 < e; j += 2) {
            float4 v0 = ((const float4*)(x + (size_t)g_ssrc[j] * D0))[lane];
            float4 v1 = ((const float4*)(x + (size_t)g_ssrc[j + 1] * D0))[lane];
            acc.x += v0.x + v1.x; acc.y += v0.y + v1.y;
            acc.z += v0.z + v1.z; acc.w += v0.w + v1.w;
        }
        if (j < e) {
            float4 v = ((const float4*)(x + (size_t)g_ssrc[j] * D0))[lane];
            acc.x += v.x; acc.y += v.y; acc.z += v.z; acc.w += v.w;
        }
        float invd = (e > s) ? 1.0f / (float)(e - s) : 0.0f;
        __half2 h0 = __floats2half2_rn(acc.x * invd, acc.y * invd);
        __half2 h1 = __floats2half2_rn(acc.z * invd, acc.w * invd);
        *(uint2*)(agg + (size_t)n * K1 + r * D0 + lane * 4) =
            make_uint2(*(uint32_t*)&h0, *(uint32_t*)&h1);
    } else if (w < NR + N_NODES) {
        int n = w - NR;
        float4 v = ((const float4*)(x + (size_t)n * D0))[lane];
        __half2 h0 = __floats2half2_rn(v.x, v.y);
        __half2 h1 = __floats2half2_rn(v.z, v.w);
        *(uint2*)(agg + (size_t)n * K1 + R_REL * D0 + lane * 4) =
            make_uint2(*(uint32_t*)&h0, *(uint32_t*)&h1);
    }
}

// layer 2: fp16 input (Din=256)
__global__ void __launch_bounds__(256) agg2_k(const __half* __restrict__ x,
                                              __half* __restrict__ agg) {
    int w = (blockIdx.x * blockDim.x + threadIdx.x) >> 5;
    int lane = threadIdx.x & 31;
    if (w < NR) {
        int n = w >> 3, r = w & 7;
        int s = g_off[w], e = g_off[w + 1];
        float acc[8];
#pragma unroll
        for (int i = 0; i < 8; ++i) acc[i] = 0.f;
        int j = s;
        for (; j + 1 < e; j += 2) {
            uint4 u0 = ((const uint4*)(x + (size_t)g_ssrc[j] * D1))[lane];
            uint4 u1 = ((const uint4*)(x + (size_t)g_ssrc[j + 1] * D1))[lane];
            float2 a0 = __half22float2(*(__half2*)&u0.x), b0 = __half22float2(*(__half2*)&u1.x);
            float2 a1 = __half22float2(*(__half2*)&u0.y), b1 = __half22float2(*(__half2*)&u1.y);
            float2 a2 = __half22float2(*(__half2*)&u0.z), b2 = __half22float2(*(__half2*)&u1.z);
            float2 a3 = __half22float2(*(__half2*)&u0.w), b3 = __half22float2(*(__half2*)&u1.w);
            acc[0] += a0.x + b0.x; acc[1] += a0.y + b0.y;
            acc[2] += a1.x + b1.x; acc[3] += a1.y + b1.y;
            acc[4] += a2.x + b2.x; acc[5] += a2.y + b2.y;
            acc[6] += a3.x + b3.x; acc[7] += a3.y + b3.y;
        }
        if (j < e) {
            uint4 u0 = ((const uint4*)(x + (size_t)g_ssrc[j] * D1))[lane];
            float2 a0 = __half22float2(*(__half2*)&u0.x);
            float2 a1 = __half22float2(*(__half2*)&u0.y);
            float2 a2 = __half22float2(*(__half2*)&u0.z);
            float2 a3 = __half22float2(*(__half2*)&u0.w);
            acc[0] += a0.x; acc[1] += a0.y; acc[2] += a1.x; acc[3] += a1.y;
            acc[4] += a2.x; acc[5] += a2.y; acc[6] += a3.x; acc[7] += a3.y;
        }
        float invd = (e > s) ? 1.0f / (float)(e - s) : 0.0f;
        __half2 h0 = __floats2half2_rn(acc[0] * invd, acc[1] * invd);
        __half2 h1 = __floats2half2_rn(acc[2] * invd, acc[3] * invd);
        __half2 h2 = __floats2half2_rn(acc[4] * invd, acc[5] * invd);
        __half2 h3 = __floats2half2_rn(acc[6] * invd, acc[7] * invd);
        *(uint4*)(agg + (size_t)n * K2 + r * D1 + lane * 8) =
            make_uint4(*(uint32_t*)&h0, *(uint32_t*)&h1,
                       *(uint32_t*)&h2, *(uint32_t*)&h3);
    } else if (w < NR + N_NODES) {
        int n = w - NR;
        uint4 v = ((const uint4*)(x + (size_t)n * D1))[lane];
        *(uint4*)(agg + (size_t)n * K2 + R_REL * D1 + lane * 8) = v;
    }
}

// ------------------------- fp16 tensor-core GEMM -------------------------
// C[M,Nn] = A[M,K] @ Bt[Nn,K]^T + bias.  fp16 in, fp32 accum/out.
// Block 128x128, BK=32, 2-stage cp.async. 8 warps (4M x 2N), warp tile 32x64.
__global__ void __launch_bounds__(256, 2) gemm_h_k(
    const __half* __restrict__ A, const __half* __restrict__ Bt,
    const float* __restrict__ bias, float* __restrict__ C,
    int M, int Nn, int K) {
    __shared__ __align__(16) __half As[2][128 * HS];
    __shared__ __align__(16) __half Bs[2][128 * HS];

    const int tid = threadIdx.x;
    const int lane = tid & 31, warp = tid >> 5;
    const int wm = warp >> 1, wn = warp & 1;
    const int gid = lane >> 2, tg = lane & 3;
    const int blockN = blockIdx.x * 128;
    const int blockM = blockIdx.y * 128;

    float acc[2][8][4];
#pragma unroll
    for (int mt = 0; mt < 2; ++mt)
#pragma unroll
        for (int nt = 0; nt < 8; ++nt)
#pragma unroll
            for (int c = 0; c < 4; ++c) acc[mt][nt][c] = 0.f;

    const int ktiles = K >> 5;

    auto load_stage = [&](int st, int kt) {
        int kbase = kt << 5;
#pragma unroll
        for (int it = 0; it < 2; ++it) {
            int idx = tid + it * 256;
            int row = idx >> 2, c16 = (idx & 3) << 3;
            int gr = blockM + row;
            int cr = gr < M ? gr : (M - 1);
            cp_async16(&As[st][row * HS + c16], A + (size_t)cr * K + kbase + c16,
                       gr < M ? 16 : 0);
            cp_async16(&Bs[st][row * HS + c16], Bt + (size_t)(blockN + row) * K + kbase + c16,
                       16);
        }
        cp_commit();
    };

    load_stage(0, 0);

    for (int kt = 0; kt < ktiles; ++kt) {
        int cur = kt & 1;
        if (kt + 1 < ktiles) {
            load_stage(cur ^ 1, kt + 1);
            asm volatile("cp.async.wait_group 1;");
        } else {
            asm volatile("cp.async.wait_group 0;");
        }
        __syncthreads();

        const __half* as = As[cur];
        const __half* bs = Bs[cur];
#pragma unroll
        for (int kk = 0; kk < 2; ++kk) {
            int k0 = kk * 16 + 2 * tg;
            uint32_t a[2][4];
#pragma unroll
            for (int mt = 0; mt < 2; ++mt) {
                int r0 = wm * 32 + mt * 16 + gid;
                a[mt][0] = *(const uint32_t*)&as[r0 * HS + k0];
                a[mt][1] = *(const uint32_t*)&as[(r0 + 8) * HS + k0];
                a[mt][2] = *(const uint32_t*)&as[r0 * HS + k0 + 8];
                a[mt][3] = *(const uint32_t*)&as[(r0 + 8) * HS + k0 + 8];
            }
            uint32_t b[8][2];
#pragma unroll
            for (int nt = 0; nt < 8; ++nt) {
                int c0 = wn * 64 + nt * 8 + gid;
                b[nt][0] = *(const uint32_t*)&bs[c0 * HS + k0];
                b[nt][1] = *(const uint32_t*)&bs[c0 * HS + k0 + 8];
            }
#pragma unroll
            for (int mt = 0; mt < 2; ++mt)
#pragma unroll
                for (int nt = 0; nt < 8; ++nt) mma_h(acc[mt][nt], a[mt], b[nt]);
        }
        __syncthreads();
    }

    // epilogue: bias + fp32 store
#pragma unroll
    for (int mt = 0; mt < 2; ++mt)
#pragma unroll
        for (int nt = 0; nt < 8; ++nt) {
            int row0 = blockM + wm * 32 + mt * 16 + gid;
            int col = blockN + wn * 64 + nt * 8 + 2 * tg;
            float bx = bias[col], by = bias[col + 1];
            if (row0 < M) {
                *(float2*)(C + (size_t)row0 * Nn + col) =
                    make_float2(acc[mt][nt][0] + bx, acc[mt][nt][1] + by);
            }
            int row1 = row0 + 8;
            if (row1 < M) {
                *(float2*)(C + (size_t)row1 * Nn + col) =
                    make_float2(acc[mt][nt][2] + bx, acc[mt][nt][3] + by);
            }
        }
}

// ------------------------- batchnorm -------------------------
__global__ void bnstats_k(const float* __restrict__ y, int C,
                          float* __restrict__ sum, float* __restrict__ sumsq) {
    int c = blockIdx.x * blockDim.x + threadIdx.x;
    float s = 0.f, q = 0.f;
    for (int row = blockIdx.y; row < N_NODES; row += gridDim.y) {
        float v = y[(size_t)row * C + c];
        s += v;
        q += v * v;
    }
    atomicAdd(&sum[c], s);
    atomicAdd(&sumsq[c], q);
}

__global__ void bnfin_k(const float* __restrict__ sum, const float* __restrict__ sumsq,
                        const float* __restrict__ gamma, const float* __restrict__ beta,
                        float* __restrict__ scale, float* __restrict__ shift, int C) {
    int c = blockIdx.x * blockDim.x + threadIdx.x;
    if (c >= C) return;
    const float invn = 1.0f / (float)N_NODES;
    float mu = sum[c] * invn;
    float var = sumsq[c] * invn - mu * mu;
    float sc = gamma[c] * rsqrtf(var + BN_EPS);
    scale[c] = sc;
    shift[c] = beta[c] - mu * sc;
}

// BN + LeakyReLU -> fp16.  C compile-time (power of two): index math is AND/shift.
// float4 loads of y, uint2 (4x fp16) stores of x.
template <int C>
__global__ void __launch_bounds__(256) bnapply_k(
    const float* __restrict__ y, const float* __restrict__ scale,
    const float* __restrict__ shift, __half* __restrict__ x) {
    const int C4 = C / 4;
    size_t total4 = (size_t)N_NODES * C4;
    size_t stride = (size_t)gridDim.x * blockDim.x;
    for (size_t i = blockIdx.x * (size_t)blockDim.x + threadIdx.x; i < total4; i += stride) {
        int c4 = (int)(i & (C4 - 1));
        int c = c4 * 4;
        float4 v = ((const float4*)y)[i];
        v.x = v.x * scale[c]     + shift[c];
        v.y = v.y * scale[c + 1] + shift[c + 1];
        v.z = v.z * scale[c + 2] + shift[c + 2];
        v.w = v.w * scale[c + 3] + shift[c + 3];
        v.x = v.x > 0.f ? v.x : ALPHA * v.x;
        v.y = v.y > 0.f ? v.y : ALPHA * v.y;
        v.z = v.z > 0.f ? v.z : ALPHA * v.z;
        v.w = v.w > 0.f ? v.w : ALPHA * v.w;
        __half2 h0 = __floats2half2_rn(v.x, v.y);
        __half2 h1 = __floats2half2_rn(v.z, v.w);
        ((uint2*)x)[i] = make_uint2(*(uint32_t*)&h0, *(uint32_t*)&h1);
    }
}

// ------------------------- host launch -------------------------
extern "C" void kernel_launch(void* const* d_in, const int* in_sizes, int n_in,
                              void* d_out, int out_size) {
    const float* emb    = (const float*)d_in[0];
    const int*   eidx   = (const int*)d_in[1];
    const int*   ety    = (const int*)d_in[2];
    const float* basis1 = (const float*)d_in[3];
    const float* comp1  = (const float*)d_in[4];
    const float* root1  = (const float*)d_in[5];
    const float* bias1  = (const float*)d_in[6];
    const float* gamma1 = (const float*)d_in[7];
    const float* beta1  = (const float*)d_in[8];
    const float* basis2 = (const float*)d_in[9];
    const float* comp2  = (const float*)d_in[10];
    const float* root2  = (const float*)d_in[11];
    const float* bias2  = (const float*)d_in[12];
    const float* gamma2 = (const float*)d_in[13];
    const float* beta2  = (const float*)d_in[14];
    const float* Wf     = (const float*)d_in[15];
    const float* bf     = (const float*)d_in[16];
    const int* srcp = eidx;
    const int* tgtp = eidx + N_EDGES;
    float* outp = (float*)d_out;

    float *W1, *W2, *y1, *y2;
    __half *Wt1, *Wt2, *Wft, *agg1, *agg2, *x1, *x2;
    float *sum1, *sumsq1, *sum2, *sumsq2, *scale1, *shift1, *scale2, *shift2;
    cudaGetSymbolAddress((void**)&W1, g_W1);
    cudaGetSymbolAddress((void**)&W2, g_W2);
    cudaGetSymbolAddress((void**)&Wt1, g_Wt1);
    cudaGetSymbolAddress((void**)&Wt2, g_Wt2);
    cudaGetSymbolAddress((void**)&Wft, g_Wft);
    cudaGetSymbolAddress((void**)&agg1, g_agg1);
    cudaGetSymbolAddress((void**)&agg2, g_agg2);
    cudaGetSymbolAddress((void**)&y1, g_y1);
    cudaGetSymbolAddress((void**)&x1, g_x1);
    cudaGetSymbolAddress((void**)&y2, g_y2);
    cudaGetSymbolAddress((void**)&x2, g_x2);
    cudaGetSymbolAddress((void**)&sum1, g_sum1);
    cudaGetSymbolAddress((void**)&sumsq1, g_sumsq1);
    cudaGetSymbolAddress((void**)&sum2, g_sum2);
    cudaGetSymbolAddress((void**)&sumsq2, g_sumsq2);
    cudaGetSymbolAddress((void**)&scale1, g_scale1);
    cudaGetSymbolAddress((void**)&shift1, g_shift1);
    cudaGetSymbolAddress((void**)&scale2, g_scale2);
    cudaGetSymbolAddress((void**)&shift2, g_shift2);

    const int TPB = 256;
    int nScanBlocks = (NR + 1023) / 1024;  // 391
    int aggBlocks = ((NR + N_NODES) * 32 + TPB - 1) / TPB;

    // CSR build
    zero_k<<<512, TPB>>>();
    hist_k<<<(N_EDGES + TPB - 1) / TPB, TPB>>>(tgtp, ety);
    scan1_k<<<nScanBlocks, 1024>>>();
    scan23_k<<<(NR + 511) / 512, 512>>>(nScanBlocks);
    scatter_k<<<(N_EDGES + TPB - 1) / TPB, TPB>>>(srcp, tgtp, ety);

    // weights: fp32 build, then transpose+fp16 convert
    build_w_k<<<(D0 * D1 + TPB - 1) / TPB, TPB>>>(basis1, comp1, root1, W1, D0, D1);
    build_w_k<<<(D1 * D2 + TPB - 1) / TPB, TPB>>>(basis2, comp2, root2, W2, D1, D2);
    transpose_h_k<<<dim3(D1 / 32, K1 / 32), dim3(32, 8)>>>(W1, Wt1, K1, D1);
    transpose_h_k<<<dim3(D2 / 32, K2 / 32), dim3(32, 8)>>>(W2, Wt2, K2, D2);
    transpose_h_k<<<dim3(D2 / 32, D2 / 32), dim3(32, 8)>>>(Wf, Wft, D2, D2);

    dim3 grid1(D1 / 128, (N_NODES + 127) / 128);
    dim3 grid2(D2 / 128, (N_NODES + 127) / 128);

    // layer 1
    agg1_k<<<aggBlocks, TPB>>>(emb, agg1);
    gemm_h_k<<<grid1, 256>>>(agg1, Wt1, bias1, y1, N_NODES, D1, K1);
    bnstats_k<<<dim3(D1 / TPB, 128), TPB>>>(y1, D1, sum1, sumsq1);
    bnfin_k<<<1, D1>>>(sum1, sumsq1, gamma1, beta1, scale1, shift1, D1);
    bnapply_k<D1><<<4096, TPB>>>(y1, scale1, shift1, x1);

    // layer 2
    agg2_k<<<aggBlocks, TPB>>>(x1, agg2);
    gemm_h_k<<<grid2, 256>>>(agg2, Wt2, bias2, y2, N_NODES, D2, K2);
    bnstats_k<<<dim3(D2 / TPB, 128), TPB>>>(y2, D2, sum2, sumsq2);
    bnfin_k<<<1, D2>>>(sum2, sumsq2, gamma2, beta2, scale2, shift2, D2);
    bnapply_k<D2><<<4096, TPB>>>(y2, scale2, shift2, x2);

    // final linear
    gemm_h_k<<<grid2, 256>>>(x2, Wft, bf, outp, N_NODES, D2, D2);
}

// round 14
// speedup vs baseline: 1.1805x; 1.0931x over previous
#include <cuda_runtime.h>
#include <cuda_fp16.h>
#include <cstdint>

#define N_NODES 50000
#define N_EDGES 800000
#define R_REL 8
#define NR (N_NODES * R_REL)
#define B_BASES 30
#define D0 128
#define D1 256
#define D2 512
#define K1 ((R_REL + 1) * D0)   // 1152
#define K2 ((R_REL + 1) * D1)   // 2304
#define BN_EPS 1e-5f
#define ALPHA 0.01f

#define HS 40                   // GEMM smem row stride in halfs (80B, 16B-aligned)
#define GSTAGES 3
#define STAGE_HALFS (128 * HS)                       // per matrix per stage
#define GSMB (GSTAGES * 2 * STAGE_HALFS * 2)         // bytes = 61440

// ------------------------- scratch (__device__ globals) -------------------------
__device__ int    g_deg[NR];
__device__ int    g_off[NR + 1];
__device__ int    g_cur[NR];
__device__ int    g_bsums[512];
__device__ int    g_ssrc[N_EDGES];
__device__ float  g_W1[(size_t)K1 * D1];       // fp32 [K,N]
__device__ float  g_W2[(size_t)K2 * D2];
__device__ __half g_Wt1[(size_t)D1 * K1];      // fp16 [N,K]
__device__ __half g_Wt2[(size_t)D2 * K2];
__device__ __half g_Wft[(size_t)D2 * D2];
__device__ __half g_agg1[(size_t)N_NODES * K1];
__device__ __half g_agg2[(size_t)N_NODES * K2];
__device__ float  g_y1[(size_t)N_NODES * D1];
__device__ __half g_x1[(size_t)N_NODES * D1];
__device__ float  g_y2[(size_t)N_NODES * D2];
__device__ __half g_x2[(size_t)N_NODES * D2];
__device__ float  g_sum1[D1], g_sumsq1[D1];
__device__ float  g_sum2[D2], g_sumsq2[D2];
__device__ float  g_scale1[D1], g_shift1[D1];
__device__ float  g_scale2[D2], g_shift2[D2];

// ------------------------- small helpers -------------------------
__device__ __forceinline__ void mma_h(float (&d)[4], const uint32_t (&a)[4],
                                      const uint32_t (&b)[2]) {
    asm volatile(
        "mma.sync.aligned.m16n8k16.row.col.f32.f16.f16.f32 "
        "{%0,%1,%2,%3}, {%4,%5,%6,%7}, {%8,%9}, {%0,%1,%2,%3};"
        : "+f"(d[0]), "+f"(d[1]), "+f"(d[2]), "+f"(d[3])
        : "r"(a[0]), "r"(a[1]), "r"(a[2]), "r"(a[3]), "r"(b[0]), "r"(b[1]));
}
__device__ __forceinline__ void cp_async16(void* smem, const void* gmem, int src_bytes) {
    uint32_t s = (uint32_t)__cvta_generic_to_shared(smem);
    asm volatile("cp.async.cg.shared.global [%0], [%1], 16, %2;"
                 :: "r"(s), "l"(gmem), "r"(src_bytes));
}
__device__ __forceinline__ void cp_commit() {
    asm volatile("cp.async.commit_group;");
}

// ------------------------- setup kernels -------------------------
__global__ void zero_k() {
    int i = blockIdx.x * blockDim.x + threadIdx.x;
    int stride = gridDim.x * blockDim.x;
    for (int j = i; j < NR; j += stride) g_deg[j] = 0;
    if (i < D1) { g_sum1[i] = 0.f; g_sumsq1[i] = 0.f; }
    if (i < D2) { g_sum2[i] = 0.f; g_sumsq2[i] = 0.f; }
}

__global__ void hist_k(const int* __restrict__ tgt, const int* __restrict__ ety) {
    int e = blockIdx.x * blockDim.x + threadIdx.x;
    if (e < N_EDGES) atomicAdd(&g_deg[tgt[e] * R_REL + ety[e]], 1);
}

__global__ void scan1_k() {
    __shared__ int s[1024];
    int t = threadIdx.x;
    int i = blockIdx.x * 1024 + t;
    int v = (i < NR) ? g_deg[i] : 0;
    s[t] = v;
    __syncthreads();
#pragma unroll
    for (int off = 1; off < 1024; off <<= 1) {
        int u = (t >= off) ? s[t - off] : 0;
        __syncthreads();
        s[t] += u;
        __syncthreads();
    }
    if (i < NR) g_off[i] = s[t] - v;
    if (t == 1023) g_bsums[blockIdx.x] = s[1023];
}

__global__ void scan23_k(int nb) {
    __shared__ int s[512];
    __shared__ int ex[512];
    int t = threadIdx.x;
    int v = (t < nb) ? g_bsums[t] : 0;
    s[t] = v;
    __syncthreads();
#pragma unroll
    for (int off = 1; off < 512; off <<= 1) {
        int u = (t >= off) ? s[t - off] : 0;
        __syncthreads();
        s[t] += u;
        __syncthreads();
    }
    ex[t] = s[t] - v;
    __syncthreads();
    for (int i = blockIdx.x * blockDim.x + t; i < NR; i += gridDim.x * blockDim.x) {
        int o = g_off[i] + ex[i >> 10];
        g_off[i] = o;
        g_cur[i] = o;
    }
    if (blockIdx.x == 0 && t == 0) g_off[NR] = N_EDGES;
}

__global__ void scatter_k(const int* __restrict__ src, const int* __restrict__ tgt,
                          const int* __restrict__ ety) {
    int e = blockIdx.x * blockDim.x + threadIdx.x;
    if (e < N_EDGES) {
        int seg = tgt[e] * R_REL + ety[e];
        int p = atomicAdd(&g_cur[seg], 1);
        g_ssrc[p] = src[e];
    }
}

// W_cat[(r*Din+i)*Dout+o] = sum_b comp[r,b]*basis[b,i,o]; root appended (fp32)
__global__ void build_w_k(const float* __restrict__ basis,
                          const float* __restrict__ comp,
                          const float* __restrict__ root,
                          float* __restrict__ W, int Din, int Dout) {
    __shared__ float sc[R_REL * B_BASES];
    if (threadIdx.x < R_REL * B_BASES) sc[threadIdx.x] = comp[threadIdx.x];
    __syncthreads();
    int idx = blockIdx.x * blockDim.x + threadIdx.x;
    int total = Din * Dout;
    if (idx >= total) return;
    float acc[R_REL];
#pragma unroll
    for (int r = 0; r < R_REL; ++r) acc[r] = 0.f;
    for (int b = 0; b < B_BASES; ++b) {
        float v = basis[(size_t)b * total + idx];
#pragma unroll
        for (int r = 0; r < R_REL; ++r) acc[r] += sc[r * B_BASES + b] * v;
    }
#pragma unroll
    for (int r = 0; r < R_REL; ++r)
        W[(size_t)r * total + idx] = acc[r];
    W[(size_t)R_REL * total + idx] = root[idx];
}

// transpose + fp16 convert: dst[n][k] = (half)src[k][n].  grid (Nd/32, Kd/32)
__global__ void transpose_h_k(const float* __restrict__ src, __half* __restrict__ dst,
                              int Kd, int Nd) {
    __shared__ float t[32][33];
    int bx = blockIdx.x * 32;   // over N
    int by = blockIdx.y * 32;   // over K
    for (int j = threadIdx.y; j < 32; j += 8)
        t[j][threadIdx.x] = src[(size_t)(by + j) * Nd + bx + threadIdx.x];
    __syncthreads();
    for (int j = threadIdx.y; j < 32; j += 8)
        dst[(size_t)(bx + j) * Kd + by + threadIdx.x] = __float2half_rn(t[threadIdx.x][j]);
}

// ------------------------- aggregation (warp per node, R10-proven) -------------------------
// layer 1: fp32 input (emb, Din=128) -> fp16 A rows [mean_r0..mean_r7 | self]
__global__ void __launch_bounds__(256) agg1_k(const float* __restrict__ x,
                                              __half* __restrict__ agg) {
    int w = (blockIdx.x * blockDim.x + threadIdx.x) >> 5;
    int lane = threadIdx.x & 31;
    if (w >= N_NODES) return;
    int base = w * R_REL;
    __half* rowbase = agg + (size_t)w * K1;
#pragma unroll 1
    for (int r = 0; r < R_REL; ++r) {
        int s = g_off[base + r];
        int e = g_off[base + r + 1];
        float4 acc = make_float4(0.f, 0.f, 0.f, 0.f);
        for (int j = s; j < e; ++j) {
            float4 v = ((const float4*)(x + (size_t)g_ssrc[j] * D0))[lane];
            acc.x += v.x; acc.y += v.y; acc.z += v.z; acc.w += v.w;
        }
        float invd = (e > s) ? 1.0f / (float)(e - s) : 0.0f;
        __half2 h0 = __floats2half2_rn(acc.x * invd, acc.y * invd);
        __half2 h1 = __floats2half2_rn(acc.z * invd, acc.w * invd);
        *(uint2*)(rowbase + r * D0 + lane * 4) =
            make_uint2(*(uint32_t*)&h0, *(uint32_t*)&h1);
    }
    {
        float4 v = ((const float4*)(x + (size_t)w * D0))[lane];
        __half2 h0 = __floats2half2_rn(v.x, v.y);
        __half2 h1 = __floats2half2_rn(v.z, v.w);
        *(uint2*)(rowbase + R_REL * D0 + lane * 4) =
            make_uint2(*(uint32_t*)&h0, *(uint32_t*)&h1);
    }
}

// layer 2: fp16 input (x1, Din=256)
__global__ void __launch_bounds__(256) agg2_k(const __half* __restrict__ x,
                                              __half* __restrict__ agg) {
    int w = (blockIdx.x * blockDim.x + threadIdx.x) >> 5;
    int lane = threadIdx.x & 31;
    if (w >= N_NODES) return;
    int base = w * R_REL;
    __half* rowbase = agg + (size_t)w * K2;
#pragma unroll 1
    for (int r = 0; r < R_REL; ++r) {
        int s = g_off[base + r];
        int e = g_off[base + r + 1];
        float acc[8];
#pragma unroll
        for (int i = 0; i < 8; ++i) acc[i] = 0.f;
        for (int j = s; j < e; ++j) {
            uint4 v = ((const uint4*)(x + (size_t)g_ssrc[j] * D1))[lane];
            float2 f0 = __half22float2(*(__half2*)&v.x);
            float2 f1 = __half22float2(*(__half2*)&v.y);
            float2 f2 = __half22float2(*(__half2*)&v.z);
            float2 f3 = __half22float2(*(__half2*)&v.w);
            acc[0] += f0.x; acc[1] += f0.y; acc[2] += f1.x; acc[3] += f1.y;
            acc[4] += f2.x; acc[5] += f2.y; acc[6] += f3.x; acc[7] += f3.y;
        }
        float invd = (e > s) ? 1.0f / (float)(e - s) : 0.0f;
        __half2 h0 = __floats2half2_rn(acc[0] * invd, acc[1] * invd);
        __half2 h1 = __floats2half2_rn(acc[2] * invd, acc[3] * invd);
        __half2 h2 = __floats2half2_rn(acc[4] * invd, acc[5] * invd);
        __half2 h3 = __floats2half2_rn(acc[6] * invd, acc[7] * invd);
        *(uint4*)(rowbase + r * D1 + lane * 8) =
            make_uint4(*(uint32_t*)&h0, *(uint32_t*)&h1,
                       *(uint32_t*)&h2, *(uint32_t*)&h3);
    }
    {
        uint4 v = ((const uint4*)(x + (size_t)w * D1))[lane];
        *(uint4*)(rowbase + R_REL * D1 + lane * 8) = v;
    }
}

// ------------------------- fp16 tensor-core GEMM (3-stage cp.async) -------------------------
// C[M,Nn] = A[M,K] @ Bt[Nn,K]^T + bias.  fp16 in, fp32 accum/out.
// Block 128x128, BK=32, 3-stage ring (dynamic smem). 8 warps (4M x 2N), warp tile 32x64.
__global__ void __launch_bounds__(256, 2) gemm_h_k(
    const __half* __restrict__ A, const __half* __restrict__ Bt,
    const float* __restrict__ bias, float* __restrict__ C,
    int M, int Nn, int K) {
    extern __shared__ __align__(16) __half smemh[];
    __half* Asm = smemh;                           // [3][128*HS]
    __half* Bsm = smemh + GSTAGES * STAGE_HALFS;   // [3][128*HS]

    const int tid = threadIdx.x;
    const int lane = tid & 31, warp = tid >> 5;
    const int wm = warp >> 1, wn = warp & 1;
    const int gid = lane >> 2, tg = lane & 3;
    const int blockN = blockIdx.x * 128;
    const int blockM = blockIdx.y * 128;

    float acc[2][8][4];
#pragma unroll
    for (int mt = 0; mt < 2; ++mt)
#pragma unroll
        for (int nt = 0; nt < 8; ++nt)
#pragma unroll
            for (int c = 0; c < 4; ++c) acc[mt][nt][c] = 0.f;

    const int ktiles = K >> 5;

    auto load_stage = [&](int st, int kt) {
        int kbase = kt << 5;
        __half* as = Asm + st * STAGE_HALFS;
        __half* bs = Bsm + st * STAGE_HALFS;
#pragma unroll
        for (int it = 0; it < 2; ++it) {
            int idx = tid + it * 256;
            int row = idx >> 2, c16 = (idx & 3) << 3;
            int gr = blockM + row;
            int cr = gr < M ? gr : (M - 1);
            cp_async16(&as[row * HS + c16], A + (size_t)cr * K + kbase + c16,
                       gr < M ? 16 : 0);
            cp_async16(&bs[row * HS + c16], Bt + (size_t)(blockN + row) * K + kbase + c16,
                       16);
        }
        cp_commit();
    };

    load_stage(0, 0);
    load_stage(1, 1);

    for (int kt = 0; kt < ktiles; ++kt) {
        int cur = kt % 3;
        if (kt + 2 < ktiles) load_stage((kt + 2) % 3, kt + 2);
        else cp_commit();   // dummy group keeps wait arithmetic uniform
        asm volatile("cp.async.wait_group 2;");
        __syncthreads();

        const __half* as = Asm + cur * STAGE_HALFS;
        const __half* bs = Bsm + cur * STAGE_HALFS;
#pragma unroll
        for (int kk = 0; kk < 2; ++kk) {
            int k0 = kk * 16 + 2 * tg;
            uint32_t a[2][4];
#pragma unroll
            for (int mt = 0; mt < 2; ++mt) {
                int r0 = wm * 32 + mt * 16 + gid;
                a[mt][0] = *(const uint32_t*)&as[r0 * HS + k0];
                a[mt][1] = *(const uint32_t*)&as[(r0 + 8) * HS + k0];
                a[mt][2] = *(const uint32_t*)&as[r0 * HS + k0 + 8];
                a[mt][3] = *(const uint32_t*)&as[(r0 + 8) * HS + k0 + 8];
            }
            uint32_t b[8][2];
#pragma unroll
            for (int nt = 0; nt < 8; ++nt) {
                int c0 = wn * 64 + nt * 8 + gid;
                b[nt][0] = *(const uint32_t*)&bs[c0 * HS + k0];
                b[nt][1] = *(const uint32_t*)&bs[c0 * HS + k0 + 8];
            }
#pragma unroll
            for (int mt = 0; mt < 2; ++mt)
#pragma unroll
                for (int nt = 0; nt < 8; ++nt) mma_h(acc[mt][nt], a[mt], b[nt]);
        }
        __syncthreads();
    }

    // epilogue: bias + fp32 store
#pragma unroll
    for (int mt = 0; mt < 2; ++mt)
#pragma unroll
        for (int nt = 0; nt < 8; ++nt) {
            int row0 = blockM + wm * 32 + mt * 16 + gid;
            int col = blockN + wn * 64 + nt * 8 + 2 * tg;
            float bx = bias[col], by = bias[col + 1];
            if (row0 < M) {
                *(float2*)(C + (size_t)row0 * Nn + col) =
                    make_float2(acc[mt][nt][0] + bx, acc[mt][nt][1] + by);
            }
            int row1 = row0 + 8;
            if (row1 < M) {
                *(float2*)(C + (size_t)row1 * Nn + col) =
                    make_float2(acc[mt][nt][2] + bx, acc[mt][nt][3] + by);
            }
        }
}

// ------------------------- batchnorm -------------------------
__global__ void bnstats_k(const float* __restrict__ y, int C,
                          float* __restrict__ sum, float* __restrict__ sumsq) {
    int c = blockIdx.x * blockDim.x + threadIdx.x;
    float s = 0.f, q = 0.f;
    for (int row = blockIdx.y; row < N_NODES; row += gridDim.y) {
        float v = y[(size_t)row * C + c];
        s += v;
        q += v * v;
    }
    atomicAdd(&sum[c], s);
    atomicAdd(&sumsq[c], q);
}

__global__ void bnfin_k(const float* __restrict__ sum, const float* __restrict__ sumsq,
                        const float* __restrict__ gamma, const float* __restrict__ beta,
                        float* __restrict__ scale, float* __restrict__ shift, int C) {
    int c = blockIdx.x * blockDim.x + threadIdx.x;
    if (c >= C) return;
    const float invn = 1.0f / (float)N_NODES;
    float mu = sum[c] * invn;
    float var = sumsq[c] * invn - mu * mu;
    float sc = gamma[c] * rsqrtf(var + BN_EPS);
    scale[c] = sc;
    shift[c] = beta[c] - mu * sc;
}

// BN + LeakyReLU -> fp16.  C compile-time power of two: index math is AND/shift.
template <int C>
__global__ void __launch_bounds__(256) bnapply_k(
    const float* __restrict__ y, const float* __restrict__ scale,
    const float* __restrict__ shift, __half* __restrict__ x) {
    const int C4 = C / 4;
    size_t total4 = (size_t)N_NODES * C4;
    size_t stride = (size_t)gridDim.x * blockDim.x;
    for (size_t i = blockIdx.x * (size_t)blockDim.x + threadIdx.x; i < total4; i += stride) {
        int c4 = (int)(i & (C4 - 1));
        int c = c4 * 4;
        float4 v = ((const float4*)y)[i];
        v.x = v.x * scale[c]     + shift[c];
        v.y = v.y * scale[c + 1] + shift[c + 1];
        v.z = v.z * scale[c + 2] + shift[c + 2];
        v.w = v.w * scale[c + 3] + shift[c + 3];
        v.x = v.x > 0.f ? v.x : ALPHA * v.x;
        v.y = v.y > 0.f ? v.y : ALPHA * v.y;
        v.z = v.z > 0.f ? v.z : ALPHA * v.z;
        v.w = v.w > 0.f ? v.w : ALPHA * v.w;
        __half2 h0 = __floats2half2_rn(v.x, v.y);
        __half2 h1 = __floats2half2_rn(v.z, v.w);
        ((uint2*)x)[i] = make_uint2(*(uint32_t*)&h0, *(uint32_t*)&h1);
    }
}

// ------------------------- host launch -------------------------
extern "C" void kernel_launch(void* const* d_in, const int* in_sizes, int n_in,
                              void* d_out, int out_size) {
    const float* emb    = (const float*)d_in[0];
    const int*   eidx   = (const int*)d_in[1];
    const int*   ety    = (const int*)d_in[2];
    const float* basis1 = (const float*)d_in[3];
    const float* comp1  = (const float*)d_in[4];
    const float* root1  = (const float*)d_in[5];
    const float* bias1  = (const float*)d_in[6];
    const float* gamma1 = (const float*)d_in[7];
    const float* beta1  = (const float*)d_in[8];
    const float* basis2 = (const float*)d_in[9];
    const float* comp2  = (const float*)d_in[10];
    const float* root2  = (const float*)d_in[11];
    const float* bias2  = (const float*)d_in[12];
    const float* gamma2 = (const float*)d_in[13];
    const float* beta2  = (const float*)d_in[14];
    const float* Wf     = (const float*)d_in[15];
    const float* bf     = (const float*)d_in[16];
    const int* srcp = eidx;
    const int* tgtp = eidx + N_EDGES;
    float* outp = (float*)d_out;

    float *W1, *W2, *y1, *y2;
    __half *Wt1, *Wt2, *Wft, *agg1, *agg2, *x1, *x2;
    float *sum1, *sumsq1, *sum2, *sumsq2, *scale1, *shift1, *scale2, *shift2;
    cudaGetSymbolAddress((void**)&W1, g_W1);
    cudaGetSymbolAddress((void**)&W2, g_W2);
    cudaGetSymbolAddress((void**)&Wt1, g_Wt1);
    cudaGetSymbolAddress((void**)&Wt2, g_Wt2);
    cudaGetSymbolAddress((void**)&Wft, g_Wft);
    cudaGetSymbolAddress((void**)&agg1, g_agg1);
    cudaGetSymbolAddress((void**)&agg2, g_agg2);
    cudaGetSymbolAddress((void**)&y1, g_y1);
    cudaGetSymbolAddress((void**)&x1, g_x1);
    cudaGetSymbolAddress((void**)&y2, g_y2);
    cudaGetSymbolAddress((void**)&x2, g_x2);
    cudaGetSymbolAddress((void**)&sum1, g_sum1);
    cudaGetSymbolAddress((void**)&sumsq1, g_sumsq1);
    cudaGetSymbolAddress((void**)&sum2, g_sum2);
    cudaGetSymbolAddress((void**)&sumsq2, g_sumsq2);
    cudaGetSymbolAddress((void**)&scale1, g_scale1);
    cudaGetSymbolAddress((void**)&shift1, g_shift1);
    cudaGetSymbolAddress((void**)&scale2, g_scale2);
    cudaGetSymbolAddress((void**)&shift2, g_shift2);

    cudaFuncSetAttribute(gemm_h_k, cudaFuncAttributeMaxDynamicSharedMemorySize, GSMB);

    const int TPB = 256;
    int nScanBlocks = (NR + 1023) / 1024;  // 391

    // CSR build
    zero_k<<<512, TPB>>>();
    hist_k<<<(N_EDGES + TPB - 1) / TPB, TPB>>>(tgtp, ety);
    scan1_k<<<nScanBlocks, 1024>>>();
    scan23_k<<<(NR + 511) / 512, 512>>>(nScanBlocks);
    scatter_k<<<(N_EDGES + TPB - 1) / TPB, TPB>>>(srcp, tgtp, ety);

    // weights: fp32 build, then transpose+fp16 convert
    build_w_k<<<(D0 * D1 + TPB - 1) / TPB, TPB>>>(basis1, comp1, root1, W1, D0, D1);
    build_w_k<<<(D1 * D2 + TPB - 1) / TPB, TPB>>>(basis2, comp2, root2, W2, D1, D2);
    transpose_h_k<<<dim3(D1 / 32, K1 / 32), dim3(32, 8)>>>(W1, Wt1, K1, D1);
    transpose_h_k<<<dim3(D2 / 32, K2 / 32), dim3(32, 8)>>>(W2, Wt2, K2, D2);
    transpose_h_k<<<dim3(D2 / 32, D2 / 32), dim3(32, 8)>>>(Wf, Wft, D2, D2);

    dim3 grid1(D1 / 128, (N_NODES + 127) / 128);
    dim3 grid2(D2 / 128, (N_NODES + 127) / 128);

    // layer 1
    agg1_k<<<(N_NODES * 32 + TPB - 1) / TPB, TPB>>>(emb, agg1);
    gemm_h_k<<<grid1, 256, GSMB>>>(agg1, Wt1, bias1, y1, N_NODES, D1, K1);
    bnstats_k<<<dim3(D1 / TPB, 128), TPB>>>(y1, D1, sum1, sumsq1);
    bnfin_k<<<1, D1>>>(sum1, sumsq1, gamma1, beta1, scale1, shift1, D1);
    bnapply_k<D1><<<4096, TPB>>>(y1, scale1, shift1, x1);

    // layer 2
    agg2_k<<<(N_NODES * 32 + TPB - 1) / TPB, TPB>>>(x1, agg2);
    gemm_h_k<<<grid2, 256, GSMB>>>(agg2, Wt2, bias2, y2, N_NODES, D2, K2);
    bnstats_k<<<dim3(D2 / TPB, 128), TPB>>>(y2, D2, sum2, sumsq2);
    bnfin_k<<<1, D2>>>(sum2, sumsq2, gamma2, beta2, scale2, shift2, D2);
    bnapply_k<D2><<<4096, TPB>>>(y2, scale2, shift2, x2);

    // final linear
    gemm_h_k<<<grid2, 256, GSMB>>>(x2, Wft, bf, outp, N_NODES, D2, D2);
}

// round 15
// speedup vs baseline: 1.2718x; 1.0773x over previous
#include <cuda_runtime.h>
#include <cuda_fp16.h>
#include <cstdint>

#define N_NODES 50000
#define N_EDGES 800000
#define R_REL 8
#define NR (N_NODES * R_REL)
#define B_BASES 30
#define D0 128
#define D1 256
#define D2 512
#define K1 ((R_REL + 1) * D0)   // 1152
#define K2 ((R_REL + 1) * D1)   // 2304
#define BN_EPS 1e-5f
#define ALPHA 0.01f

#define HS 40                   // GEMM smem row stride in halfs (80B, 16B-aligned)
#define GSTAGES 3
#define STAGE_HALFS (128 * HS)                       // per matrix per stage
#define GSMB (GSTAGES * 2 * STAGE_HALFS * 2)         // bytes = 61440

// ------------------------- scratch (__device__ globals) -------------------------
__device__ int    g_deg[NR];
__device__ int    g_off[NR + 1];
__device__ int    g_cur[NR];
__device__ int    g_bsums[512];
__device__ int    g_ssrc[N_EDGES];
__device__ float  g_W1[(size_t)K1 * D1];       // fp32 [K,N]
__device__ float  g_W2[(size_t)K2 * D2];
__device__ __half g_Wt1[(size_t)D1 * K1];      // fp16 [N,K]
__device__ __half g_Wt2[(size_t)D2 * K2];
__device__ __half g_Wft[(size_t)D2 * D2];
__device__ __half g_agg1[(size_t)N_NODES * K1];
__device__ __half g_agg2[(size_t)N_NODES * K2];
__device__ float  g_y1[(size_t)N_NODES * D1];
__device__ __half g_x1[(size_t)N_NODES * D1];
__device__ float  g_y2[(size_t)N_NODES * D2];
__device__ __half g_x2[(size_t)N_NODES * D2];
__device__ float  g_sum1[D1], g_sumsq1[D1];
__device__ float  g_sum2[D2], g_sumsq2[D2];
__device__ float  g_scale1[D1], g_shift1[D1];
__device__ float  g_scale2[D2], g_shift2[D2];

// ------------------------- small helpers -------------------------
__device__ __forceinline__ void mma_h(float (&d)[4], const uint32_t (&a)[4],
                                      const uint32_t (&b)[2]) {
    asm volatile(
        "mma.sync.aligned.m16n8k16.row.col.f32.f16.f16.f32 "
        "{%0,%1,%2,%3}, {%4,%5,%6,%7}, {%8,%9}, {%0,%1,%2,%3};"
        : "+f"(d[0]), "+f"(d[1]), "+f"(d[2]), "+f"(d[3])
        : "r"(a[0]), "r"(a[1]), "r"(a[2]), "r"(a[3]), "r"(b[0]), "r"(b[1]));
}
__device__ __forceinline__ void cp_async16(void* smem, const void* gmem, int src_bytes) {
    uint32_t s = (uint32_t)__cvta_generic_to_shared(smem);
    asm volatile("cp.async.cg.shared.global [%0], [%1], 16, %2;"
                 :: "r"(s), "l"(gmem), "r"(src_bytes));
}
__device__ __forceinline__ void cp_commit() {
    asm volatile("cp.async.commit_group;");
}

// ------------------------- setup kernels -------------------------
__global__ void zero_k() {
    int i = blockIdx.x * blockDim.x + threadIdx.x;
    int stride = gridDim.x * blockDim.x;
    for (int j = i; j < NR; j += stride) g_deg[j] = 0;
    if (i < D1) { g_sum1[i] = 0.f; g_sumsq1[i] = 0.f; }
    if (i < D2) { g_sum2[i] = 0.f; g_sumsq2[i] = 0.f; }
}

__global__ void hist_k(const int* __restrict__ tgt, const int* __restrict__ ety) {
    int e = blockIdx.x * blockDim.x + threadIdx.x;
    if (e < N_EDGES) atomicAdd(&g_deg[tgt[e] * R_REL + ety[e]], 1);
}

__global__ void scan1_k() {
    __shared__ int s[1024];
    int t = threadIdx.x;
    int i = blockIdx.x * 1024 + t;
    int v = (i < NR) ? g_deg[i] : 0;
    s[t] = v;
    __syncthreads();
#pragma unroll
    for (int off = 1; off < 1024; off <<= 1) {
        int u = (t >= off) ? s[t - off] : 0;
        __syncthreads();
        s[t] += u;
        __syncthreads();
    }
    if (i < NR) g_off[i] = s[t] - v;
    if (t == 1023) g_bsums[blockIdx.x] = s[1023];
}

__global__ void scan23_k(int nb) {
    __shared__ int s[512];
    __shared__ int ex[512];
    int t = threadIdx.x;
    int v = (t < nb) ? g_bsums[t] : 0;
    s[t] = v;
    __syncthreads();
#pragma unroll
    for (int off = 1; off < 512; off <<= 1) {
        int u = (t >= off) ? s[t - off] : 0;
        __syncthreads();
        s[t] += u;
        __syncthreads();
    }
    ex[t] = s[t] - v;
    __syncthreads();
    for (int i = blockIdx.x * blockDim.x + t; i < NR; i += gridDim.x * blockDim.x) {
        int o = g_off[i] + ex[i >> 10];
        g_off[i] = o;
        g_cur[i] = o;
    }
    if (blockIdx.x == 0 && t == 0) g_off[NR] = N_EDGES;
}

__global__ void scatter_k(const int* __restrict__ src, const int* __restrict__ tgt,
                          const int* __restrict__ ety) {
    int e = blockIdx.x * blockDim.x + threadIdx.x;
    if (e < N_EDGES) {
        int seg = tgt[e] * R_REL + ety[e];
        int p = atomicAdd(&g_cur[seg], 1);
        g_ssrc[p] = src[e];
    }
}

// W_cat[(r*Din+i)*Dout+o] = sum_b comp[r,b]*basis[b,i,o]; root appended (fp32)
__global__ void build_w_k(const float* __restrict__ basis,
                          const float* __restrict__ comp,
                          const float* __restrict__ root,
                          float* __restrict__ W, int Din, int Dout) {
    __shared__ float sc[R_REL * B_BASES];
    if (threadIdx.x < R_REL * B_BASES) sc[threadIdx.x] = comp[threadIdx.x];
    __syncthreads();
    int idx = blockIdx.x * blockDim.x + threadIdx.x;
    int total = Din * Dout;
    if (idx >= total) return;
    float acc[R_REL];
#pragma unroll
    for (int r = 0; r < R_REL; ++r) acc[r] = 0.f;
    for (int b = 0; b < B_BASES; ++b) {
        float v = basis[(size_t)b * total + idx];
#pragma unroll
        for (int r = 0; r < R_REL; ++r) acc[r] += sc[r * B_BASES + b] * v;
    }
#pragma unroll
    for (int r = 0; r < R_REL; ++r)
        W[(size_t)r * total + idx] = acc[r];
    W[(size_t)R_REL * total + idx] = root[idx];
}

// transpose + fp16 convert: dst[n][k] = (half)src[k][n].  grid (Nd/32, Kd/32)
__global__ void transpose_h_k(const float* __restrict__ src, __half* __restrict__ dst,
                              int Kd, int Nd) {
    __shared__ float t[32][33];
    int bx = blockIdx.x * 32;   // over N
    int by = blockIdx.y * 32;   // over K
    for (int j = threadIdx.y; j < 32; j += 8)
        t[j][threadIdx.x] = src[(size_t)(by + j) * Nd + bx + threadIdx.x];
    __syncthreads();
    for (int j = threadIdx.y; j < 32; j += 8)
        dst[(size_t)(bx + j) * Kd + by + threadIdx.x] = __float2half_rn(t[threadIdx.x][j]);
}

// ------------------------- aggregation (warp per node, R10-proven) -------------------------
// layer 1: fp32 input (emb, Din=128) -> fp16 A rows [mean_r0..mean_r7 | self]
__global__ void __launch_bounds__(256) agg1_k(const float* __restrict__ x,
                                              __half* __restrict__ agg) {
    int w = (blockIdx.x * blockDim.x + threadIdx.x) >> 5;
    int lane = threadIdx.x & 31;
    if (w >= N_NODES) return;
    int base = w * R_REL;
    __half* rowbase = agg + (size_t)w * K1;
#pragma unroll 1
    for (int r = 0; r < R_REL; ++r) {
        int s = g_off[base + r];
        int e = g_off[base + r + 1];
        float4 acc = make_float4(0.f, 0.f, 0.f, 0.f);
        for (int j = s; j < e; ++j) {
            float4 v = ((const float4*)(x + (size_t)g_ssrc[j] * D0))[lane];
            acc.x += v.x; acc.y += v.y; acc.z += v.z; acc.w += v.w;
        }
        float invd = (e > s) ? 1.0f / (float)(e - s) : 0.0f;
        __half2 h0 = __floats2half2_rn(acc.x * invd, acc.y * invd);
        __half2 h1 = __floats2half2_rn(acc.z * invd, acc.w * invd);
        *(uint2*)(rowbase + r * D0 + lane * 4) =
            make_uint2(*(uint32_t*)&h0, *(uint32_t*)&h1);
    }
    {
        float4 v = ((const float4*)(x + (size_t)w * D0))[lane];
        __half2 h0 = __floats2half2_rn(v.x, v.y);
        __half2 h1 = __floats2half2_rn(v.z, v.w);
        *(uint2*)(rowbase + R_REL * D0 + lane * 4) =
            make_uint2(*(uint32_t*)&h0, *(uint32_t*)&h1);
    }
}

// layer 2: fp16 input (x1, Din=256)
__global__ void __launch_bounds__(256) agg2_k(const __half* __restrict__ x,
                                              __half* __restrict__ agg) {
    int w = (blockIdx.x * blockDim.x + threadIdx.x) >> 5;
    int lane = threadIdx.x & 31;
    if (w >= N_NODES) return;
    int base = w * R_REL;
    __half* rowbase = agg + (size_t)w * K2;
#pragma unroll 1
    for (int r = 0; r < R_REL; ++r) {
        int s = g_off[base + r];
        int e = g_off[base + r + 1];
        float acc[8];
#pragma unroll
        for (int i = 0; i < 8; ++i) acc[i] = 0.f;
        for (int j = s; j < e; ++j) {
            uint4 v = ((const uint4*)(x + (size_t)g_ssrc[j] * D1))[lane];
            float2 f0 = __half22float2(*(__half2*)&v.x);
            float2 f1 = __half22float2(*(__half2*)&v.y);
            float2 f2 = __half22float2(*(__half2*)&v.z);
            float2 f3 = __half22float2(*(__half2*)&v.w);
            acc[0] += f0.x; acc[1] += f0.y; acc[2] += f1.x; acc[3] += f1.y;
            acc[4] += f2.x; acc[5] += f2.y; acc[6] += f3.x; acc[7] += f3.y;
        }
        float invd = (e > s) ? 1.0f / (float)(e - s) : 0.0f;
        __half2 h0 = __floats2half2_rn(acc[0] * invd, acc[1] * invd);
        __half2 h1 = __floats2half2_rn(acc[2] * invd, acc[3] * invd);
        __half2 h2 = __floats2half2_rn(acc[4] * invd, acc[5] * invd);
        __half2 h3 = __floats2half2_rn(acc[6] * invd, acc[7] * invd);
        *(uint4*)(rowbase + r * D1 + lane * 8) =
            make_uint4(*(uint32_t*)&h0, *(uint32_t*)&h1,
                       *(uint32_t*)&h2, *(uint32_t*)&h3);
    }
    {
        uint4 v = ((const uint4*)(x + (size_t)w * D1))[lane];
        *(uint4*)(rowbase + R_REL * D1 + lane * 8) = v;
    }
}

// ------------------------- fp16 tensor-core GEMM (3-stage cp.async) -------------------------
// C[M,Nn] = A[M,K] @ Bt[Nn,K]^T + bias.  fp16 in, fp32 accum/out.
// Block 128x128, BK=32, 3-stage ring (dynamic smem). 8 warps (4M x 2N), warp tile 32x64.
// STATS: fused BN column sums — shuffle-reduced over gid, then 4 conflict-free
// smem atomics per warp per nt, one global atomic per column per CTA.
template <bool STATS>
__global__ void __launch_bounds__(256, 2) gemm_h_k(
    const __half* __restrict__ A, const __half* __restrict__ Bt,
    const float* __restrict__ bias, float* __restrict__ C,
    float* __restrict__ gsum, float* __restrict__ gsumsq,
    int M, int Nn, int K) {
    extern __shared__ __align__(16) __half smemh[];
    __half* Asm = smemh;                           // [3][128*HS]
    __half* Bsm = smemh + GSTAGES * STAGE_HALFS;   // [3][128*HS]

    const int tid = threadIdx.x;
    const int lane = tid & 31, warp = tid >> 5;
    const int wm = warp >> 1, wn = warp & 1;
    const int gid = lane >> 2, tg = lane & 3;
    const int blockN = blockIdx.x * 128;
    const int blockM = blockIdx.y * 128;

    float acc[2][8][4];
#pragma unroll
    for (int mt = 0; mt < 2; ++mt)
#pragma unroll
        for (int nt = 0; nt < 8; ++nt)
#pragma unroll
            for (int c = 0; c < 4; ++c) acc[mt][nt][c] = 0.f;

    const int ktiles = K >> 5;

    auto load_stage = [&](int st, int kt) {
        int kbase = kt << 5;
        __half* as = Asm + st * STAGE_HALFS;
        __half* bs = Bsm + st * STAGE_HALFS;
#pragma unroll
        for (int it = 0; it < 2; ++it) {
            int idx = tid + it * 256;
            int row = idx >> 2, c16 = (idx & 3) << 3;
            int gr = blockM + row;
            int cr = gr < M ? gr : (M - 1);
            cp_async16(&as[row * HS + c16], A + (size_t)cr * K + kbase + c16,
                       gr < M ? 16 : 0);
            cp_async16(&bs[row * HS + c16], Bt + (size_t)(blockN + row) * K + kbase + c16,
                       16);
        }
        cp_commit();
    };

    load_stage(0, 0);
    load_stage(1, 1);

    for (int kt = 0; kt < ktiles; ++kt) {
        int cur = kt % 3;
        if (kt + 2 < ktiles) load_stage((kt + 2) % 3, kt + 2);
        else cp_commit();   // dummy group keeps wait arithmetic uniform
        asm volatile("cp.async.wait_group 2;");
        __syncthreads();

        const __half* as = Asm + cur * STAGE_HALFS;
        const __half* bs = Bsm + cur * STAGE_HALFS;
#pragma unroll
        for (int kk = 0; kk < 2; ++kk) {
            int k0 = kk * 16 + 2 * tg;
            uint32_t a[2][4];
#pragma unroll
            for (int mt = 0; mt < 2; ++mt) {
                int r0 = wm * 32 + mt * 16 + gid;
                a[mt][0] = *(const uint32_t*)&as[r0 * HS + k0];
                a[mt][1] = *(const uint32_t*)&as[(r0 + 8) * HS + k0];
                a[mt][2] = *(const uint32_t*)&as[r0 * HS + k0 + 8];
                a[mt][3] = *(const uint32_t*)&as[(r0 + 8) * HS + k0 + 8];
            }
            uint32_t b[8][2];
#pragma unroll
            for (int nt = 0; nt < 8; ++nt) {
                int c0 = wn * 64 + nt * 8 + gid;
                b[nt][0] = *(const uint32_t*)&bs[c0 * HS + k0];
                b[nt][1] = *(const uint32_t*)&bs[c0 * HS + k0 + 8];
            }
#pragma unroll
            for (int mt = 0; mt < 2; ++mt)
#pragma unroll
                for (int nt = 0; nt < 8; ++nt) mma_h(acc[mt][nt], a[mt], b[nt]);
        }
        __syncthreads();
    }

    // epilogue: bias + fp32 store (+ optional shuffle-reduced BN stats)
    float* colsum = (float*)Asm;     // stage memory dead after final sync
    float* colsq = colsum + 128;
    if (STATS) {
        if (tid < 128) { colsum[tid] = 0.f; colsq[tid] = 0.f; }
        __syncthreads();
    }
#pragma unroll
    for (int nt = 0; nt < 8; ++nt) {
        int cb = wn * 64 + nt * 8 + 2 * tg;
        int col = blockN + cb;
        float bx = bias[col], by = bias[col + 1];
        float s0 = 0.f, q0 = 0.f, s1 = 0.f, q1 = 0.f;
#pragma unroll
        for (int mt = 0; mt < 2; ++mt) {
            int row0 = blockM + wm * 32 + mt * 16 + gid;
            if (row0 < M) {
                float v0 = acc[mt][nt][0] + bx;
                float v1 = acc[mt][nt][1] + by;
                *(float2*)(C + (size_t)row0 * Nn + col) = make_float2(v0, v1);
                if (STATS) { s0 += v0; q0 += v0 * v0; s1 += v1; q1 += v1 * v1; }
            }
            int row1 = row0 + 8;
            if (row1 < M) {
                float v0 = acc[mt][nt][2] + bx;
                float v1 = acc[mt][nt][3] + by;
                *(float2*)(C + (size_t)row1 * Nn + col) = make_float2(v0, v1);
                if (STATS) { s0 += v0; q0 += v0 * v0; s1 += v1; q1 += v1 * v1; }
            }
        }
        if (STATS) {
            // butterfly-reduce over gid (lane bits 2..4); tg (column) invariant
#pragma unroll
            for (int m = 4; m <= 16; m <<= 1) {
                s0 += __shfl_xor_sync(0xFFFFFFFFu, s0, m);
                q0 += __shfl_xor_sync(0xFFFFFFFFu, q0, m);
                s1 += __shfl_xor_sync(0xFFFFFFFFu, s1, m);
                q1 += __shfl_xor_sync(0xFFFFFFFFu, q1, m);
            }
            if (gid == 0) {   // 4 lanes, distinct addresses (per tg)
                atomicAdd(&colsum[cb], s0);
                atomicAdd(&colsq[cb], q0);
                atomicAdd(&colsum[cb + 1], s1);
                atomicAdd(&colsq[cb + 1], q1);
            }
        }
    }
    if (STATS) {
        __syncthreads();
        if (tid < 128) {
            atomicAdd(&gsum[blockN + tid], colsum[tid]);
            atomicAdd(&gsumsq[blockN + tid], colsq[tid]);
        }
    }
}

// ------------------------- batchnorm finalize + apply -------------------------
__global__ void bnfin_k(const float* __restrict__ sum, const float* __restrict__ sumsq,
                        const float* __restrict__ gamma, const float* __restrict__ beta,
                        float* __restrict__ scale, float* __restrict__ shift, int C) {
    int c = blockIdx.x * blockDim.x + threadIdx.x;
    if (c >= C) return;
    const float invn = 1.0f / (float)N_NODES;
    float mu = sum[c] * invn;
    float var = sumsq[c] * invn - mu * mu;
    float sc = gamma[c] * rsqrtf(var + BN_EPS);
    scale[c] = sc;
    shift[c] = beta[c] - mu * sc;
}

// BN + LeakyReLU -> fp16.  C compile-time power of two: index math is AND/shift.
template <int C>
__global__ void __launch_bounds__(256) bnapply_k(
    const float* __restrict__ y, const float* __restrict__ scale,
    const float* __restrict__ shift, __half* __restrict__ x) {
    const int C4 = C / 4;
    size_t total4 = (size_t)N_NODES * C4;
    size_t stride = (size_t)gridDim.x * blockDim.x;
    for (size_t i = blockIdx.x * (size_t)blockDim.x + threadIdx.x; i < total4; i += stride) {
        int c4 = (int)(i & (C4 - 1));
        int c = c4 * 4;
        float4 v = ((const float4*)y)[i];
        v.x = v.x * scale[c]     + shift[c];
        v.y = v.y * scale[c + 1] + shift[c + 1];
        v.z = v.z * scale[c + 2] + shift[c + 2];
        v.w = v.w * scale[c + 3] + shift[c + 3];
        v.x = v.x > 0.f ? v.x : ALPHA * v.x;
        v.y = v.y > 0.f ? v.y : ALPHA * v.y;
        v.z = v.z > 0.f ? v.z : ALPHA * v.z;
        v.w = v.w > 0.f ? v.w : ALPHA * v.w;
        __half2 h0 = __floats2half2_rn(v.x, v.y);
        __half2 h1 = __floats2half2_rn(v.z, v.w);
        ((uint2*)x)[i] = make_uint2(*(uint32_t*)&h0, *(uint32_t*)&h1);
    }
}

// ------------------------- host launch -------------------------
extern "C" void kernel_launch(void* const* d_in, const int* in_sizes, int n_in,
                              void* d_out, int out_size) {
    const float* emb    = (const float*)d_in[0];
    const int*   eidx   = (const int*)d_in[1];
    const int*   ety    = (const int*)d_in[2];
    const float* basis1 = (const float*)d_in[3];
    const float* comp1  = (const float*)d_in[4];
    const float* root1  = (const float*)d_in[5];
    const float* bias1  = (const float*)d_in[6];
    const float* gamma1 = (const float*)d_in[7];
    const float* beta1  = (const float*)d_in[8];
    const float* basis2 = (const float*)d_in[9];
    const float* comp2  = (const float*)d_in[10];
    const float* root2  = (const float*)d_in[11];
    const float* bias2  = (const float*)d_in[12];
    const float* gamma2 = (const float*)d_in[13];
    const float* beta2  = (const float*)d_in[14];
    const float* Wf     = (const float*)d_in[15];
    const float* bf     = (const float*)d_in[16];
    const int* srcp = eidx;
    const int* tgtp = eidx + N_EDGES;
    float* outp = (float*)d_out;

    float *W1, *W2, *y1, *y2;
    __half *Wt1, *Wt2, *Wft, *agg1, *agg2, *x1, *x2;
    float *sum1, *sumsq1, *sum2, *sumsq2, *scale1, *shift1, *scale2, *shift2;
    cudaGetSymbolAddress((void**)&W1, g_W1);
    cudaGetSymbolAddress((void**)&W2, g_W2);
    cudaGetSymbolAddress((void**)&Wt1, g_Wt1);
    cudaGetSymbolAddress((void**)&Wt2, g_Wt2);
    cudaGetSymbolAddress((void**)&Wft, g_Wft);
    cudaGetSymbolAddress((void**)&agg1, g_agg1);
    cudaGetSymbolAddress((void**)&agg2, g_agg2);
    cudaGetSymbolAddress((void**)&y1, g_y1);
    cudaGetSymbolAddress((void**)&x1, g_x1);
    cudaGetSymbolAddress((void**)&y2, g_y2);
    cudaGetSymbolAddress((void**)&x2, g_x2);
    cudaGetSymbolAddress((void**)&sum1, g_sum1);
    cudaGetSymbolAddress((void**)&sumsq1, g_sumsq1);
    cudaGetSymbolAddress((void**)&sum2, g_sum2);
    cudaGetSymbolAddress((void**)&sumsq2, g_sumsq2);
    cudaGetSymbolAddress((void**)&scale1, g_scale1);
    cudaGetSymbolAddress((void**)&shift1, g_shift1);
    cudaGetSymbolAddress((void**)&scale2, g_scale2);
    cudaGetSymbolAddress((void**)&shift2, g_shift2);

    cudaFuncSetAttribute(gemm_h_k<true>, cudaFuncAttributeMaxDynamicSharedMemorySize, GSMB);
    cudaFuncSetAttribute(gemm_h_k<false>, cudaFuncAttributeMaxDynamicSharedMemorySize, GSMB);

    const int TPB = 256;
    int nScanBlocks = (NR + 1023) / 1024;  // 391

    // CSR build
    zero_k<<<512, TPB>>>();
    hist_k<<<(N_EDGES + TPB - 1) / TPB, TPB>>>(tgtp, ety);
    scan1_k<<<nScanBlocks, 1024>>>();
    scan23_k<<<(NR + 511) / 512, 512>>>(nScanBlocks);
    scatter_k<<<(N_EDGES + TPB - 1) / TPB, TPB>>>(srcp, tgtp, ety);

    // weights: fp32 build, then transpose+fp16 convert
    build_w_k<<<(D0 * D1 + TPB - 1) / TPB, TPB>>>(basis1, comp1, root1, W1, D0, D1);
    build_w_k<<<(D1 * D2 + TPB - 1) / TPB, TPB>>>(basis2, comp2, root2, W2, D1, D2);
    transpose_h_k<<<dim3(D1 / 32, K1 / 32), dim3(32, 8)>>>(W1, Wt1, K1, D1);
    transpose_h_k<<<dim3(D2 / 32, K2 / 32), dim3(32, 8)>>>(W2, Wt2, K2, D2);
    transpose_h_k<<<dim3(D2 / 32, D2 / 32), dim3(32, 8)>>>(Wf, Wft, D2, D2);

    dim3 grid1(D1 / 128, (N_NODES + 127) / 128);
    dim3 grid2(D2 / 128, (N_NODES + 127) / 128);

    // layer 1: agg -> GEMM(+fused stats) -> finalize -> apply
    agg1_k<<<(N_NODES * 32 + TPB - 1) / TPB, TPB>>>(emb, agg1);
    gemm_h_k<true><<<grid1, 256, GSMB>>>(agg1, Wt1, bias1, y1, sum1, sumsq1,
                                         N_NODES, D1, K1);
    bnfin_k<<<1, D1>>>(sum1, sumsq1, gamma1, beta1, scale1, shift1, D1);
    bnapply_k<D1><<<4096, TPB>>>(y1, scale1, shift1, x1);

    // layer 2
    agg2_k<<<(N_NODES * 32 + TPB - 1) / TPB, TPB>>>(x1, agg2);
    gemm_h_k<true><<<grid2, 256, GSMB>>>(agg2, Wt2, bias2, y2, sum2, sumsq2,
                                         N_NODES, D2, K2);
    bnfin_k<<<1, D2>>>(sum2, sumsq2, gamma2, beta2, scale2, shift2, D2);
    bnapply_k<D2><<<4096, TPB>>>(y2, scale2, shift2, x2);

    // final linear
    gemm_h_k<false><<<grid2, 256, GSMB>>>(x2, Wft, bf, outp, nullptr, nullptr,
                                          N_NODES, D2, D2);
}

// round 16
// speedup vs baseline: 1.2982x; 1.0208x over previous
#include <cuda_runtime.h>
#include <cuda_fp16.h>
#include <cstdint>

#define N_NODES 50000
#define N_EDGES 800000
#define R_REL 8
#define NR (N_NODES * R_REL)
#define B_BASES 30
#define D0 128
#define D1 256
#define D2 512
#define K1 ((R_REL + 1) * D0)   // 1152
#define K2 ((R_REL + 1) * D1)   // 2304
#define BN_EPS 1e-5f
#define ALPHA 0.01f

#define HS 40                   // GEMM smem row stride in halfs (80B, 16B-aligned)
#define GSTAGES 3
#define STAGE_HALFS (128 * HS)                       // per matrix per stage
#define GSMB (GSTAGES * 2 * STAGE_HALFS * 2)         // bytes = 61440

// ------------------------- scratch (__device__ globals) -------------------------
__device__ int    g_deg[NR];
__device__ int    g_off[NR + 1];
__device__ int    g_cur[NR];
__device__ int    g_bsums[512];
__device__ int    g_ssrc[N_EDGES];
__device__ float  g_W1[(size_t)K1 * D1];       // fp32 [K,N]
__device__ float  g_W2[(size_t)K2 * D2];
__device__ __half g_Wt1[(size_t)D1 * K1];      // fp16 [N,K]
__device__ __half g_Wt2[(size_t)D2 * K2];
__device__ __half g_Wft[(size_t)D2 * D2];
__device__ __half g_agg1[(size_t)N_NODES * K1];
__device__ __half g_agg2[(size_t)N_NODES * K2];
__device__ __half g_y1[(size_t)N_NODES * D1];  // pre-BN activations (fp16)
__device__ __half g_x1[(size_t)N_NODES * D1];
__device__ __half g_y2[(size_t)N_NODES * D2];
__device__ __half g_x2[(size_t)N_NODES * D2];
__device__ float  g_sum1[D1], g_sumsq1[D1];
__device__ float  g_sum2[D2], g_sumsq2[D2];
__device__ float  g_scale1[D1], g_shift1[D1];
__device__ float  g_scale2[D2], g_shift2[D2];

// ------------------------- small helpers -------------------------
__device__ __forceinline__ void mma_h(float (&d)[4], const uint32_t (&a)[4],
                                      const uint32_t (&b)[2]) {
    asm volatile(
        "mma.sync.aligned.m16n8k16.row.col.f32.f16.f16.f32 "
        "{%0,%1,%2,%3}, {%4,%5,%6,%7}, {%8,%9}, {%0,%1,%2,%3};"
        : "+f"(d[0]), "+f"(d[1]), "+f"(d[2]), "+f"(d[3])
        : "r"(a[0]), "r"(a[1]), "r"(a[2]), "r"(a[3]), "r"(b[0]), "r"(b[1]));
}
__device__ __forceinline__ void cp_async16(void* smem, const void* gmem, int src_bytes) {
    uint32_t s = (uint32_t)__cvta_generic_to_shared(smem);
    asm volatile("cp.async.cg.shared.global [%0], [%1], 16, %2;"
                 :: "r"(s), "l"(gmem), "r"(src_bytes));
}
__device__ __forceinline__ void cp_commit() {
    asm volatile("cp.async.commit_group;");
}

// ------------------------- setup kernels -------------------------
__global__ void zero_k() {
    int i = blockIdx.x * blockDim.x + threadIdx.x;
    int stride = gridDim.x * blockDim.x;
    for (int j = i; j < NR; j += stride) g_deg[j] = 0;
    if (i < D1) { g_sum1[i] = 0.f; g_sumsq1[i] = 0.f; }
    if (i < D2) { g_sum2[i] = 0.f; g_sumsq2[i] = 0.f; }
}

__global__ void hist_k(const int* __restrict__ tgt, const int* __restrict__ ety) {
    int e = blockIdx.x * blockDim.x + threadIdx.x;
    if (e < N_EDGES) atomicAdd(&g_deg[tgt[e] * R_REL + ety[e]], 1);
}

__global__ void scan1_k() {
    __shared__ int s[1024];
    int t = threadIdx.x;
    int i = blockIdx.x * 1024 + t;
    int v = (i < NR) ? g_deg[i] : 0;
    s[t] = v;
    __syncthreads();
#pragma unroll
    for (int off = 1; off < 1024; off <<= 1) {
        int u = (t >= off) ? s[t - off] : 0;
        __syncthreads();
        s[t] += u;
        __syncthreads();
    }
    if (i < NR) g_off[i] = s[t] - v;
    if (t == 1023) g_bsums[blockIdx.x] = s[1023];
}

__global__ void scan23_k(int nb) {
    __shared__ int s[512];
    __shared__ int ex[512];
    int t = threadIdx.x;
    int v = (t < nb) ? g_bsums[t] : 0;
    s[t] = v;
    __syncthreads();
#pragma unroll
    for (int off = 1; off < 512; off <<= 1) {
        int u = (t >= off) ? s[t - off] : 0;
        __syncthreads();
        s[t] += u;
        __syncthreads();
    }
    ex[t] = s[t] - v;
    __syncthreads();
    for (int i = blockIdx.x * blockDim.x + t; i < NR; i += gridDim.x * blockDim.x) {
        int o = g_off[i] + ex[i >> 10];
        g_off[i] = o;
        g_cur[i] = o;
    }
    if (blockIdx.x == 0 && t == 0) g_off[NR] = N_EDGES;
}

__global__ void scatter_k(const int* __restrict__ src, const int* __restrict__ tgt,
                          const int* __restrict__ ety) {
    int e = blockIdx.x * blockDim.x + threadIdx.x;
    if (e < N_EDGES) {
        int seg = tgt[e] * R_REL + ety[e];
        int p = atomicAdd(&g_cur[seg], 1);
        g_ssrc[p] = src[e];
    }
}

// W_cat[(r*Din+i)*Dout+o] = sum_b comp[r,b]*basis[b,i,o]; root appended (fp32)
__global__ void build_w_k(const float* __restrict__ basis,
                          const float* __restrict__ comp,
                          const float* __restrict__ root,
                          float* __restrict__ W, int Din, int Dout) {
    __shared__ float sc[R_REL * B_BASES];
    if (threadIdx.x < R_REL * B_BASES) sc[threadIdx.x] = comp[threadIdx.x];
    __syncthreads();
    int idx = blockIdx.x * blockDim.x + threadIdx.x;
    int total = Din * Dout;
    if (idx >= total) return;
    float acc[R_REL];
#pragma unroll
    for (int r = 0; r < R_REL; ++r) acc[r] = 0.f;
    for (int b = 0; b < B_BASES; ++b) {
        float v = basis[(size_t)b * total + idx];
#pragma unroll
        for (int r = 0; r < R_REL; ++r) acc[r] += sc[r * B_BASES + b] * v;
    }
#pragma unroll
    for (int r = 0; r < R_REL; ++r)
        W[(size_t)r * total + idx] = acc[r];
    W[(size_t)R_REL * total + idx] = root[idx];
}

// transpose + fp16 convert: dst[n][k] = (half)src[k][n].  grid (Nd/32, Kd/32)
__global__ void transpose_h_k(const float* __restrict__ src, __half* __restrict__ dst,
                              int Kd, int Nd) {
    __shared__ float t[32][33];
    int bx = blockIdx.x * 32;   // over N
    int by = blockIdx.y * 32;   // over K
    for (int j = threadIdx.y; j < 32; j += 8)
        t[j][threadIdx.x] = src[(size_t)(by + j) * Nd + bx + threadIdx.x];
    __syncthreads();
    for (int j = threadIdx.y; j < 32; j += 8)
        dst[(size_t)(bx + j) * Kd + by + threadIdx.x] = __float2half_rn(t[threadIdx.x][j]);
}

// ------------------------- aggregation (warp per node, R10-proven) -------------------------
// layer 1: fp32 input (emb, Din=128) -> fp16 A rows [mean_r0..mean_r7 | self]
__global__ void __launch_bounds__(256) agg1_k(const float* __restrict__ x,
                                              __half* __restrict__ agg) {
    int w = (blockIdx.x * blockDim.x + threadIdx.x) >> 5;
    int lane = threadIdx.x & 31;
    if (w >= N_NODES) return;
    int base = w * R_REL;
    __half* rowbase = agg + (size_t)w * K1;
#pragma unroll 1
    for (int r = 0; r < R_REL; ++r) {
        int s = g_off[base + r];
        int e = g_off[base + r + 1];
        float4 acc = make_float4(0.f, 0.f, 0.f, 0.f);
        for (int j = s; j < e; ++j) {
            float4 v = ((const float4*)(x + (size_t)g_ssrc[j] * D0))[lane];
            acc.x += v.x; acc.y += v.y; acc.z += v.z; acc.w += v.w;
        }
        float invd = (e > s) ? 1.0f / (float)(e - s) : 0.0f;
        __half2 h0 = __floats2half2_rn(acc.x * invd, acc.y * invd);
        __half2 h1 = __floats2half2_rn(acc.z * invd, acc.w * invd);
        *(uint2*)(rowbase + r * D0 + lane * 4) =
            make_uint2(*(uint32_t*)&h0, *(uint32_t*)&h1);
    }
    {
        float4 v = ((const float4*)(x + (size_t)w * D0))[lane];
        __half2 h0 = __floats2half2_rn(v.x, v.y);
        __half2 h1 = __floats2half2_rn(v.z, v.w);
        *(uint2*)(rowbase + R_REL * D0 + lane * 4) =
            make_uint2(*(uint32_t*)&h0, *(uint32_t*)&h1);
    }
}

// layer 2: fp16 input (x1, Din=256)
__global__ void __launch_bounds__(256) agg2_k(const __half* __restrict__ x,
                                              __half* __restrict__ agg) {
    int w = (blockIdx.x * blockDim.x + threadIdx.x) >> 5;
    int lane = threadIdx.x & 31;
    if (w >= N_NODES) return;
    int base = w * R_REL;
    __half* rowbase = agg + (size_t)w * K2;
#pragma unroll 1
    for (int r = 0; r < R_REL; ++r) {
        int s = g_off[base + r];
        int e = g_off[base + r + 1];
        float acc[8];
#pragma unroll
        for (int i = 0; i < 8; ++i) acc[i] = 0.f;
        for (int j = s; j < e; ++j) {
            uint4 v = ((const uint4*)(x + (size_t)g_ssrc[j] * D1))[lane];
            float2 f0 = __half22float2(*(__half2*)&v.x);
            float2 f1 = __half22float2(*(__half2*)&v.y);
            float2 f2 = __half22float2(*(__half2*)&v.z);
            float2 f3 = __half22float2(*(__half2*)&v.w);
            acc[0] += f0.x; acc[1] += f0.y; acc[2] += f1.x; acc[3] += f1.y;
            acc[4] += f2.x; acc[5] += f2.y; acc[6] += f3.x; acc[7] += f3.y;
        }
        float invd = (e > s) ? 1.0f / (float)(e - s) : 0.0f;
        __half2 h0 = __floats2half2_rn(acc[0] * invd, acc[1] * invd);
        __half2 h1 = __floats2half2_rn(acc[2] * invd, acc[3] * invd);
        __half2 h2 = __floats2half2_rn(acc[4] * invd, acc[5] * invd);
        __half2 h3 = __floats2half2_rn(acc[6] * invd, acc[7] * invd);
        *(uint4*)(rowbase + r * D1 + lane * 8) =
            make_uint4(*(uint32_t*)&h0, *(uint32_t*)&h1,
                       *(uint32_t*)&h2, *(uint32_t*)&h3);
    }
    {
        uint4 v = ((const uint4*)(x + (size_t)w * D1))[lane];
        *(uint4*)(rowbase + R_REL * D1 + lane * 8) = v;
    }
}

// ------------------------- fp16 tensor-core GEMM (3-stage cp.async) -------------------------
// C[M,Nn] = A[M,K] @ Bt[Nn,K]^T + bias.  fp16 in, fp32 accum, TOUT out.
// Block 128x128, BK=32, 3-stage ring (dynamic smem). 8 warps (4M x 2N), warp tile 32x64.
// STATS: fused BN column sums — shuffle-reduced over gid (stats from fp32 accs,
// exact), then 4 conflict-free smem atomics per warp per nt, one global atomic
// per column per CTA.
template <bool STATS, typename TOUT>
__global__ void __launch_bounds__(256, 2) gemm_h_k(
    const __half* __restrict__ A, const __half* __restrict__ Bt,
    const float* __restrict__ bias, TOUT* __restrict__ C,
    float* __restrict__ gsum, float* __restrict__ gsumsq,
    int M, int Nn, int K) {
    extern __shared__ __align__(16) __half smemh[];
    __half* Asm = smemh;                           // [3][128*HS]
    __half* Bsm = smemh + GSTAGES * STAGE_HALFS;   // [3][128*HS]

    const int tid = threadIdx.x;
    const int lane = tid & 31, warp = tid >> 5;
    const int wm = warp >> 1, wn = warp & 1;
    const int gid = lane >> 2, tg = lane & 3;
    const int blockN = blockIdx.x * 128;
    const int blockM = blockIdx.y * 128;

    float acc[2][8][4];
#pragma unroll
    for (int mt = 0; mt < 2; ++mt)
#pragma unroll
        for (int nt = 0; nt < 8; ++nt)
#pragma unroll
            for (int c = 0; c < 4; ++c) acc[mt][nt][c] = 0.f;

    const int ktiles = K >> 5;

    auto load_stage = [&](int st, int kt) {
        int kbase = kt << 5;
        __half* as = Asm + st * STAGE_HALFS;
        __half* bs = Bsm + st * STAGE_HALFS;
#pragma unroll
        for (int it = 0; it < 2; ++it) {
            int idx = tid + it * 256;
            int row = idx >> 2, c16 = (idx & 3) << 3;
            int gr = blockM + row;
            int cr = gr < M ? gr : (M - 1);
            cp_async16(&as[row * HS + c16], A + (size_t)cr * K + kbase + c16,
                       gr < M ? 16 : 0);
            cp_async16(&bs[row * HS + c16], Bt + (size_t)(blockN + row) * K + kbase + c16,
                       16);
        }
        cp_commit();
    };

    load_stage(0, 0);
    load_stage(1, 1);

    for (int kt = 0; kt < ktiles; ++kt) {
        int cur = kt % 3;
        if (kt + 2 < ktiles) load_stage((kt + 2) % 3, kt + 2);
        else cp_commit();   // dummy group keeps wait arithmetic uniform
        asm volatile("cp.async.wait_group 2;");
        __syncthreads();

        const __half* as = Asm + cur * STAGE_HALFS;
        const __half* bs = Bsm + cur * STAGE_HALFS;
#pragma unroll
        for (int kk = 0; kk < 2; ++kk) {
            int k0 = kk * 16 + 2 * tg;
            uint32_t a[2][4];
#pragma unroll
            for (int mt = 0; mt < 2; ++mt) {
                int r0 = wm * 32 + mt * 16 + gid;
                a[mt][0] = *(const uint32_t*)&as[r0 * HS + k0];
                a[mt][1] = *(const uint32_t*)&as[(r0 + 8) * HS + k0];
                a[mt][2] = *(const uint32_t*)&as[r0 * HS + k0 + 8];
                a[mt][3] = *(const uint32_t*)&as[(r0 + 8) * HS + k0 + 8];
            }
            uint32_t b[8][2];
#pragma unroll
            for (int nt = 0; nt < 8; ++nt) {
                int c0 = wn * 64 + nt * 8 + gid;
                b[nt][0] = *(const uint32_t*)&bs[c0 * HS + k0];
                b[nt][1] = *(const uint32_t*)&bs[c0 * HS + k0 + 8];
            }
#pragma unroll
            for (int mt = 0; mt < 2; ++mt)
#pragma unroll
                for (int nt = 0; nt < 8; ++nt) mma_h(acc[mt][nt], a[mt], b[nt]);
        }
        __syncthreads();
    }

    // epilogue: bias + store (+ optional shuffle-reduced BN stats)
    float* colsum = (float*)Asm;     // stage memory dead after final sync
    float* colsq = colsum + 128;
    if (STATS) {
        if (tid < 128) { colsum[tid] = 0.f; colsq[tid] = 0.f; }
        __syncthreads();
    }
#pragma unroll
    for (int nt = 0; nt < 8; ++nt) {
        int cb = wn * 64 + nt * 8 + 2 * tg;
        int col = blockN + cb;
        float bx = bias[col], by = bias[col + 1];
        float s0 = 0.f, q0 = 0.f, s1 = 0.f, q1 = 0.f;
#pragma unroll
        for (int mt = 0; mt < 2; ++mt) {
            int row0 = blockM + wm * 32 + mt * 16 + gid;
            if (row0 < M) {
                float v0 = acc[mt][nt][0] + bx;
                float v1 = acc[mt][nt][1] + by;
                if constexpr (sizeof(TOUT) == 2) {
                    *(__half2*)((__half*)C + (size_t)row0 * Nn + col) =
                        __floats2half2_rn(v0, v1);
                } else {
                    *(float2*)((float*)C + (size_t)row0 * Nn + col) = make_float2(v0, v1);
                }
                if (STATS) { s0 += v0; q0 += v0 * v0; s1 += v1; q1 += v1 * v1; }
            }
            int row1 = row0 + 8;
            if (row1 < M) {
                float v0 = acc[mt][nt][2] + bx;
                float v1 = acc[mt][nt][3] + by;
                if constexpr (sizeof(TOUT) == 2) {
                    *(__half2*)((__half*)C + (size_t)row1 * Nn + col) =
                        __floats2half2_rn(v0, v1);
                } else {
                    *(float2*)((float*)C + (size_t)row1 * Nn + col) = make_float2(v0, v1);
                }
                if (STATS) { s0 += v0; q0 += v0 * v0; s1 += v1; q1 += v1 * v1; }
            }
        }
        if (STATS) {
            // butterfly-reduce over gid (lane bits 2..4); tg (column) invariant
#pragma unroll
            for (int m = 4; m <= 16; m <<= 1) {
                s0 += __shfl_xor_sync(0xFFFFFFFFu, s0, m);
                q0 += __shfl_xor_sync(0xFFFFFFFFu, q0, m);
                s1 += __shfl_xor_sync(0xFFFFFFFFu, s1, m);
                q1 += __shfl_xor_sync(0xFFFFFFFFu, q1, m);
            }
            if (gid == 0) {   // 4 lanes, distinct addresses (per tg)
                atomicAdd(&colsum[cb], s0);
                atomicAdd(&colsq[cb], q0);
                atomicAdd(&colsum[cb + 1], s1);
                atomicAdd(&colsq[cb + 1], q1);
            }
        }
    }
    if (STATS) {
        __syncthreads();
        if (tid < 128) {
            atomicAdd(&gsum[blockN + tid], colsum[tid]);
            atomicAdd(&gsumsq[blockN + tid], colsq[tid]);
        }
    }
}

// ------------------------- batchnorm finalize + apply -------------------------
__global__ void bnfin_k(const float* __restrict__ sum, const float* __restrict__ sumsq,
                        const float* __restrict__ gamma, const float* __restrict__ beta,
                        float* __restrict__ scale, float* __restrict__ shift, int C) {
    int c = blockIdx.x * blockDim.x + threadIdx.x;
    if (c >= C) return;
    const float invn = 1.0f / (float)N_NODES;
    float mu = sum[c] * invn;
    float var = sumsq[c] * invn - mu * mu;
    float sc = gamma[c] * rsqrtf(var + BN_EPS);
    scale[c] = sc;
    shift[c] = beta[c] - mu * sc;
}

// BN + LeakyReLU: fp16 y -> fp16 x.  C compile-time power of two.
template <int C>
__global__ void __launch_bounds__(256) bnapply_k(
    const __half* __restrict__ y, const float* __restrict__ scale,
    const float* __restrict__ shift, __half* __restrict__ x) {
    const int C4 = C / 4;
    size_t total4 = (size_t)N_NODES * C4;
    size_t stride = (size_t)gridDim.x * blockDim.x;
    for (size_t i = blockIdx.x * (size_t)blockDim.x + threadIdx.x; i < total4; i += stride) {
        int c4 = (int)(i & (C4 - 1));
        int c = c4 * 4;
        uint2 u = ((const uint2*)y)[i];
        float2 f0 = __half22float2(*(__half2*)&u.x);
        float2 f1 = __half22float2(*(__half2*)&u.y);
        float4 v = make_float4(f0.x, f0.y, f1.x, f1.y);
        v.x = v.x * scale[c]     + shift[c];
        v.y = v.y * scale[c + 1] + shift[c + 1];
        v.z = v.z * scale[c + 2] + shift[c + 2];
        v.w = v.w * scale[c + 3] + shift[c + 3];
        v.x = v.x > 0.f ? v.x : ALPHA * v.x;
        v.y = v.y > 0.f ? v.y : ALPHA * v.y;
        v.z = v.z > 0.f ? v.z : ALPHA * v.z;
        v.w = v.w > 0.f ? v.w : ALPHA * v.w;
        __half2 h0 = __floats2half2_rn(v.x, v.y);
        __half2 h1 = __floats2half2_rn(v.z, v.w);
        ((uint2*)x)[i] = make_uint2(*(uint32_t*)&h0, *(uint32_t*)&h1);
    }
}

// ------------------------- host launch -------------------------
extern "C" void kernel_launch(void* const* d_in, const int* in_sizes, int n_in,
                              void* d_out, int out_size) {
    const float* emb    = (const float*)d_in[0];
    const int*   eidx   = (const int*)d_in[1];
    const int*   ety    = (const int*)d_in[2];
    const float* basis1 = (const float*)d_in[3];
    const float* comp1  = (const float*)d_in[4];
    const float* root1  = (const float*)d_in[5];
    const float* bias1  = (const float*)d_in[6];
    const float* gamma1 = (const float*)d_in[7];
    const float* beta1  = (const float*)d_in[8];
    const float* basis2 = (const float*)d_in[9];
    const float* comp2  = (const float*)d_in[10];
    const float* root2  = (const float*)d_in[11];
    const float* bias2  = (const float*)d_in[12];
    const float* gamma2 = (const float*)d_in[13];
    const float* beta2  = (const float*)d_in[14];
    const float* Wf     = (const float*)d_in[15];
    const float* bf     = (const float*)d_in[16];
    const int* srcp = eidx;
    const int* tgtp = eidx + N_EDGES;
    float* outp = (float*)d_out;

    float *W1, *W2;
    __half *Wt1, *Wt2, *Wft, *agg1, *agg2, *y1, *x1, *y2, *x2;
    float *sum1, *sumsq1, *sum2, *sumsq2, *scale1, *shift1, *scale2, *shift2;
    cudaGetSymbolAddress((void**)&W1, g_W1);
    cudaGetSymbolAddress((void**)&W2, g_W2);
    cudaGetSymbolAddress((void**)&Wt1, g_Wt1);
    cudaGetSymbolAddress((void**)&Wt2, g_Wt2);
    cudaGetSymbolAddress((void**)&Wft, g_Wft);
    cudaGetSymbolAddress((void**)&agg1, g_agg1);
    cudaGetSymbolAddress((void**)&agg2, g_agg2);
    cudaGetSymbolAddress((void**)&y1, g_y1);
    cudaGetSymbolAddress((void**)&x1, g_x1);
    cudaGetSymbolAddress((void**)&y2, g_y2);
    cudaGetSymbolAddress((void**)&x2, g_x2);
    cudaGetSymbolAddress((void**)&sum1, g_sum1);
    cudaGetSymbolAddress((void**)&sumsq1, g_sumsq1);
    cudaGetSymbolAddress((void**)&sum2, g_sum2);
    cudaGetSymbolAddress((void**)&sumsq2, g_sumsq2);
    cudaGetSymbolAddress((void**)&scale1, g_scale1);
    cudaGetSymbolAddress((void**)&shift1, g_shift1);
    cudaGetSymbolAddress((void**)&scale2, g_scale2);
    cudaGetSymbolAddress((void**)&shift2, g_shift2);

    cudaFuncSetAttribute((const void*)gemm_h_k<true, __half>,
                         cudaFuncAttributeMaxDynamicSharedMemorySize, GSMB);
    cudaFuncSetAttribute((const void*)gemm_h_k<false, float>,
                         cudaFuncAttributeMaxDynamicSharedMemorySize, GSMB);

    const int TPB = 256;
    int nScanBlocks = (NR + 1023) / 1024;  // 391

    // CSR build
    zero_k<<<512, TPB>>>();
    hist_k<<<(N_EDGES + TPB - 1) / TPB, TPB>>>(tgtp, ety);
    scan1_k<<<nScanBlocks, 1024>>>();
    scan23_k<<<(NR + 511) / 512, 512>>>(nScanBlocks);
    scatter_k<<<(N_EDGES + TPB - 1) / TPB, TPB>>>(srcp, tgtp, ety);

    // weights: fp32 build, then transpose+fp16 convert
    build_w_k<<<(D0 * D1 + TPB - 1) / TPB, TPB>>>(basis1, comp1, root1, W1, D0, D1);
    build_w_k<<<(D1 * D2 + TPB - 1) / TPB, TPB>>>(basis2, comp2, root2, W2, D1, D2);
    transpose_h_k<<<dim3(D1 / 32, K1 / 32), dim3(32, 8)>>>(W1, Wt1, K1, D1);
    transpose_h_k<<<dim3(D2 / 32, K2 / 32), dim3(32, 8)>>>(W2, Wt2, K2, D2);
    transpose_h_k<<<dim3(D2 / 32, D2 / 32), dim3(32, 8)>>>(Wf, Wft, D2, D2);

    dim3 grid1(D1 / 128, (N_NODES + 127) / 128);
    dim3 grid2(D2 / 128, (N_NODES + 127) / 128);

    // layer 1: agg -> GEMM(+fused stats, fp16 out) -> finalize -> apply
    agg1_k<<<(N_NODES * 32 + TPB - 1) / TPB, TPB>>>(emb, agg1);
    gemm_h_k<true, __half><<<grid1, 256, GSMB>>>(agg1, Wt1, bias1, y1, sum1, sumsq1,
                                                 N_NODES, D1, K1);
    bnfin_k<<<1, D1>>>(sum1, sumsq1, gamma1, beta1, scale1, shift1, D1);
    bnapply_k<D1><<<4096, TPB>>>(y1, scale1, shift1, x1);

    // layer 2
    agg2_k<<<(N_NODES * 32 + TPB - 1) / TPB, TPB>>>(x1, agg2);
    gemm_h_k<true, __half><<<grid2, 256, GSMB>>>(agg2, Wt2, bias2, y2, sum2, sumsq2,
                                                 N_NODES, D2, K2);
    bnfin_k<<<1, D2>>>(sum2, sumsq2, gamma2, beta2, scale2, shift2, D2);
    bnapply_k<D2><<<4096, TPB>>>(y2, scale2, shift2, x2);

    // final linear (fp32 out to harness buffer)
    gemm_h_k<false, float><<<grid2, 256, GSMB>>>(x2, Wft, bf, outp, nullptr, nullptr,
                                                 N_NODES, D2, D2);
}